// round 11
// baseline (speedup 1.0000x reference)
#include <cuda_runtime.h>
#include <cuda_bf16.h>
#include <math.h>

#define BB   4
#define SS   2048
#define EMB  512
#define NH   8
#define DK   64
#define BSROWS (BB*SS)   // 8192
#define BH   (BB*NH)     // 32
#define NCT  (SS/64)     // 32 col tiles in scores

// projection outputs
__device__ __nv_bfloat16 g_qh[BH * SS * DK];
__device__ __nv_bfloat16 g_ql[BH * SS * DK];
__device__ __nv_bfloat16 g_kh[BH * SS * DK];
__device__ __nv_bfloat16 g_kl[BH * SS * DK];
__device__ __nv_bfloat16 g_vh[BH * SS * DK];       // plain bf16 (precision budget)
// pre-split / pre-converted inputs
__device__ __nv_bfloat16 g_inqh[BSROWS * EMB], g_inql[BSROWS * EMB];
__device__ __nv_bfloat16 g_inkh[BSROWS * EMB], g_inkl[BSROWS * EMB];
__device__ __nv_bfloat16 g_invh[BSROWS * EMB];
// weights
__device__ __nv_bfloat16 g_wqh[EMB * EMB], g_wql[EMB * EMB];
__device__ __nv_bfloat16 g_wkh[EMB * EMB], g_wkl[EMB * EMB];
__device__ __nv_bfloat16 g_wvh[EMB * EMB];
__device__ __nv_bfloat16 g_woh[EMB * EMB];
// context (plain bf16) + pre-LN sum
__device__ __nv_bfloat16 g_ctxh[BSROWS * EMB];
__device__ float g_x[BSROWS * EMB];
// softmax stats
__device__ float g_smax[(size_t)BH * SS * NCT];
__device__ float g_ssum[(size_t)BH * SS * NCT];
__device__ float g_rowm[(size_t)BH * SS];
__device__ float g_rinv[(size_t)BH * SS];

// ---------------------------------------------------------------------------
// helpers
// ---------------------------------------------------------------------------
__device__ __forceinline__ unsigned sptr(const void* p) {
    return (unsigned)__cvta_generic_to_shared(p);
}
__device__ __forceinline__ void ldsm4(unsigned* r, unsigned a) {
    asm volatile("ldmatrix.sync.aligned.m8n8.x4.shared.b16 {%0,%1,%2,%3}, [%4];"
                 : "=r"(r[0]), "=r"(r[1]), "=r"(r[2]), "=r"(r[3]) : "r"(a));
}
__device__ __forceinline__ void ldsm4t(unsigned* r, unsigned a) {
    asm volatile("ldmatrix.sync.aligned.m8n8.x4.trans.shared.b16 {%0,%1,%2,%3}, [%4];"
                 : "=r"(r[0]), "=r"(r[1]), "=r"(r[2]), "=r"(r[3]) : "r"(a));
}
__device__ __forceinline__ void mma_bf16(float* c, const unsigned* a, const unsigned* b) {
    asm volatile(
        "mma.sync.aligned.m16n8k16.row.col.f32.bf16.bf16.f32 "
        "{%0,%1,%2,%3},{%4,%5,%6,%7},{%8,%9},{%0,%1,%2,%3};"
        : "+f"(c[0]), "+f"(c[1]), "+f"(c[2]), "+f"(c[3])
        : "r"(a[0]), "r"(a[1]), "r"(a[2]), "r"(a[3]), "r"(b[0]), "r"(b[1]));
}
__device__ __forceinline__ void split_pair(float x, float y,
                                           __nv_bfloat162& h2, __nv_bfloat162& l2) {
    __nv_bfloat16 hx = __float2bfloat16_rn(x);
    __nv_bfloat16 hy = __float2bfloat16_rn(y);
    __nv_bfloat16 lx = __float2bfloat16_rn(x - __bfloat162float(hx));
    __nv_bfloat16 ly = __float2bfloat16_rn(y - __bfloat162float(hy));
    h2 = __halves2bfloat162(hx, hy);
    l2 = __halves2bfloat162(lx, ly);
}
__device__ __forceinline__ void cp16(unsigned dst, const void* src) {
    asm volatile("cp.async.cg.shared.global [%0], [%1], 16;" :: "r"(dst), "l"(src));
}
__device__ __forceinline__ void cp_commit() {
    asm volatile("cp.async.commit_group;");
}
__device__ __forceinline__ void cp_wait0() {
    asm volatile("cp.async.wait_group 0;");
}
__device__ __forceinline__ void cp_wait1() {
    asm volatile("cp.async.wait_group 1;");
}

// ---------------------------------------------------------------------------
// Batched conversions. split3: Q,K -> hi/lo; V -> hi.  wsplit: Wq,Wk hi/lo,
// Wv,Wo hi only. One launch each.
// ---------------------------------------------------------------------------
__global__ __launch_bounds__(256) void split_inputs(
    const float* __restrict__ Q, const float* __restrict__ K,
    const float* __restrict__ V, int n4)
{
    int i = blockIdx.x * blockDim.x + threadIdx.x;
    if (i >= n4 * 3) return;
    int which = i / n4, j = i - which * n4;
    const float* in = which == 0 ? Q : which == 1 ? K : V;
    float4 v = ((const float4*)in)[j];
    __nv_bfloat162 h2, l2, h3, l3;
    split_pair(v.x, v.y, h2, l2);
    split_pair(v.z, v.w, h3, l3);
    __nv_bfloat16* hi = which == 0 ? g_inqh : which == 1 ? g_inkh : g_invh;
    ((__nv_bfloat162*)hi)[j * 2]     = h2;
    ((__nv_bfloat162*)hi)[j * 2 + 1] = h3;
    if (which < 2) {
        __nv_bfloat16* lo = which == 0 ? g_inql : g_inkl;
        ((__nv_bfloat162*)lo)[j * 2]     = l2;
        ((__nv_bfloat162*)lo)[j * 2 + 1] = l3;
    }
}

__global__ __launch_bounds__(256) void split_weights(
    const float* __restrict__ Wq, const float* __restrict__ Wk,
    const float* __restrict__ Wv, const float* __restrict__ Wo, int n4)
{
    int i = blockIdx.x * blockDim.x + threadIdx.x;
    if (i >= n4 * 4) return;
    int which = i / n4, j = i - which * n4;
    const float* in = which == 0 ? Wq : which == 1 ? Wk : which == 2 ? Wv : Wo;
    float4 v = ((const float4*)in)[j];
    __nv_bfloat162 h2, l2, h3, l3;
    split_pair(v.x, v.y, h2, l2);
    split_pair(v.z, v.w, h3, l3);
    __nv_bfloat16* hi = which == 0 ? g_wqh : which == 1 ? g_wkh
                      : which == 2 ? g_wvh : g_woh;
    ((__nv_bfloat162*)hi)[j * 2]     = h2;
    ((__nv_bfloat162*)hi)[j * 2 + 1] = h3;
    if (which < 2) {
        __nv_bfloat16* lo = which == 0 ? g_wql : g_wkl;
        ((__nv_bfloat162*)lo)[j * 2]     = l2;
        ((__nv_bfloat162*)lo)[j * 2 + 1] = l3;
    }
}

// ---------------------------------------------------------------------------
// Scores: per (b,h) 128x64 tile of q @ k^T * 0.125, masked, fp32 to attn.
// Split (3-product) MMA; coalesced smem-restaged epilogue + row stats.
// ---------------------------------------------------------------------------
#define SC_QH 0
#define SC_QL 18432
#define SC_KH 36864
#define SC_KL 46080
#define SC_SMEM 55296

__global__ __launch_bounds__(256, 3) void mma_scores(
    const unsigned char* __restrict__ mask, float* __restrict__ attn)
{
    extern __shared__ __align__(16) char smem_raw[];
    __nv_bfloat16 (*Qh)[72] = (__nv_bfloat16(*)[72])(smem_raw + SC_QH);
    __nv_bfloat16 (*Ql)[72] = (__nv_bfloat16(*)[72])(smem_raw + SC_QL);
    __nv_bfloat16 (*Kh)[72] = (__nv_bfloat16(*)[72])(smem_raw + SC_KH);
    __nv_bfloat16 (*Kl)[72] = (__nv_bfloat16(*)[72])(smem_raw + SC_KL);

    const int t = threadIdx.x, lane = t & 31, w = t >> 5;
    const int wm = w & 3, wn = w >> 2;
    const int bh = blockIdx.z, b = bh >> 3;
    const int r0 = blockIdx.y * 128, c0 = blockIdx.x * 64;
    const size_t base = (size_t)bh * SS * DK;

    #pragma unroll
    for (int i = 0; i < 12; i++) {
        int ch = t + i * 256;
        if (ch < 1024) {
            int r = ch >> 3, c8 = (ch & 7) * 8;
            cp16(sptr(&Qh[r][c8]), g_qh + base + (size_t)(r0 + r) * 64 + c8);
        } else if (ch < 2048) {
            int idx = ch - 1024, r = idx >> 3, c8 = (idx & 7) * 8;
            cp16(sptr(&Ql[r][c8]), g_ql + base + (size_t)(r0 + r) * 64 + c8);
        } else if (ch < 2560) {
            int idx = ch - 2048, r = idx >> 3, c8 = (idx & 7) * 8;
            cp16(sptr(&Kh[r][c8]), g_kh + base + (size_t)(c0 + r) * 64 + c8);
        } else {
            int idx = ch - 2560, r = idx >> 3, c8 = (idx & 7) * 8;
            cp16(sptr(&Kl[r][c8]), g_kl + base + (size_t)(c0 + r) * 64 + c8);
        }
    }
    cp_commit();
    cp_wait0();
    __syncthreads();

    float acc[2][4][4] = {};
    #pragma unroll
    for (int k2 = 0; k2 < 64; k2 += 16) {
        unsigned ah[2][4], al[2][4];
        #pragma unroll
        for (int mi = 0; mi < 2; mi++) {
            int r = wm * 32 + mi * 16 + (lane & 15);
            int c = k2 + ((lane >> 4) << 3);
            ldsm4(ah[mi], sptr(&Qh[r][c]));
            ldsm4(al[mi], sptr(&Ql[r][c]));
        }
        #pragma unroll
        for (int g = 0; g < 2; g++) {
            int nr = wn * 32 + g * 16 + (lane & 7) + ((lane >> 4) << 3);
            int kc = k2 + (((lane >> 3) & 1) << 3);
            unsigned bh_[4], bl_[4];
            ldsm4(bh_, sptr(&Kh[nr][kc]));
            ldsm4(bl_, sptr(&Kl[nr][kc]));
            #pragma unroll
            for (int mi = 0; mi < 2; mi++) {
                mma_bf16(acc[mi][2*g],   ah[mi], &bh_[0]);
                mma_bf16(acc[mi][2*g+1], ah[mi], &bh_[2]);
                mma_bf16(acc[mi][2*g],   ah[mi], &bl_[0]);
                mma_bf16(acc[mi][2*g+1], ah[mi], &bl_[2]);
                mma_bf16(acc[mi][2*g],   al[mi], &bh_[0]);
                mma_bf16(acc[mi][2*g+1], al[mi], &bh_[2]);
            }
        }
    }

    // restage through smem: [128][68] fp32, halves at col offsets 0/34
    __syncthreads();
    float* stg = (float*)smem_raw;
    #pragma unroll
    for (int mi = 0; mi < 2; mi++) {
        #pragma unroll
        for (int nf = 0; nf < 4; nf++) {
            float* c = acc[mi][nf];
            int r = wm * 32 + mi * 16 + (lane >> 2);
            int cc = wn * 34 + nf * 8 + (lane & 3) * 2;
            *(float2*)&stg[r * 68 + cc]       = make_float2(c[0], c[1]);
            *(float2*)&stg[(r + 8) * 68 + cc] = make_float2(c[2], c[3]);
        }
    }
    __syncthreads();

    {
        const int colg = lane * 2;
        const int colp = colg + (lane >= 16 ? 2 : 0);
        #pragma unroll 4
        for (int r = 0; r < 16; r++) {
            int row = w * 16 + r;
            float2 v = *(float2*)&stg[row * 68 + colp];
            size_t gr = (size_t)(r0 + row);
            const unsigned char* mp = mask + ((size_t)b * SS + gr) * SS + c0 + colg;
            v.x = mp[0] ? -1e9f : v.x * 0.125f;
            v.y = mp[1] ? -1e9f : v.y * 0.125f;
            *(float2*)(attn + ((size_t)bh * SS + gr) * SS + c0 + colg) = v;
            float mx = fmaxf(v.x, v.y);
            #pragma unroll
            for (int o = 16; o; o >>= 1) mx = fmaxf(mx, __shfl_xor_sync(0xffffffffu, mx, o));
            float s = __expf(v.x - mx) + __expf(v.y - mx);
            #pragma unroll
            for (int o = 16; o; o >>= 1) s += __shfl_xor_sync(0xffffffffu, s, o);
            if (lane == 0) {
                size_t idx = ((size_t)bh * SS + gr) * NCT + blockIdx.x;
                g_smax[idx] = mx;
                g_ssum[idx] = s;
            }
        }
    }
}

// ---------------------------------------------------------------------------
// Combine tile stats into per-row max and 1/sum. One warp per row.
// ---------------------------------------------------------------------------
__global__ __launch_bounds__(256) void softmax_stats(
    float* __restrict__ rowm, float* __restrict__ rinv)
{
    const int w = threadIdx.x >> 5, lane = threadIdx.x & 31;
    const size_t rg = (size_t)blockIdx.x * 8 + w;
    float m_l = g_smax[rg * NCT + lane];
    float s_l = g_ssum[rg * NCT + lane];
    float m = m_l;
    #pragma unroll
    for (int o = 16; o; o >>= 1) m = fmaxf(m, __shfl_xor_sync(0xffffffffu, m, o));
    float c = __expf(m_l - m) * s_l;
    #pragma unroll
    for (int o = 16; o; o >>= 1) c += __shfl_xor_sync(0xffffffffu, c, o);
    if (lane == 0) { rowm[rg] = m; rinv[rg] = 1.0f / c; }
}

// ---------------------------------------------------------------------------
// GEMM: C = A[M,512] @ W[512,512] + bias (+resid). Block 128x64, 256 thr,
// double-buffered cp.async. SPLIT=1: 3-product hi/lo; SPLIT=0: plain bf16.
// ---------------------------------------------------------------------------
template<int SPLIT>
struct GOff {
    static const unsigned AH = 0;
    static const unsigned AL = 20480;
    static const unsigned WH = SPLIT ? 40960u : 20480u;
    static const unsigned WL = 50176;
    static const unsigned ABUF = 10240;
    static const unsigned WBUF = 4608;
    static const unsigned SMEM = SPLIT ? 59392u : 29696u;
};

template<int SPLIT>
__device__ __forceinline__ void gload(
    unsigned sb, int buf,
    const __nv_bfloat16* __restrict__ Ah, const __nv_bfloat16* __restrict__ Al,
    const __nv_bfloat16* __restrict__ Wh, const __nv_bfloat16* __restrict__ Wl,
    int row0, int col0, int kk, int t)
{
    #pragma unroll
    for (int i = 0; i < 2; i++) {
        int ch = t + i * 256;
        int r = ch >> 2, c = (ch & 3) * 8;
        unsigned off = buf * GOff<SPLIT>::ABUF + r * 80 + c * 2;
        cp16(sb + GOff<SPLIT>::AH + off, Ah + (size_t)(row0 + r) * 512 + kk + c);
        if (SPLIT)
            cp16(sb + GOff<SPLIT>::AL + off, Al + (size_t)(row0 + r) * 512 + kk + c);
    }
    {
        int r = t >> 3, c = (t & 7) * 8;
        unsigned off = buf * GOff<SPLIT>::WBUF + r * 144 + c * 2;
        cp16(sb + GOff<SPLIT>::WH + off, Wh + (size_t)(kk + r) * 512 + col0 + c);
        if (SPLIT)
            cp16(sb + GOff<SPLIT>::WL + off, Wl + (size_t)(kk + r) * 512 + col0 + c);
    }
}

template<int OUTPROJ, int SPLIT, int OUTLO>
__global__ __launch_bounds__(256, 3) void mma_gemm512(
    const __nv_bfloat16* __restrict__ Ah, const __nv_bfloat16* __restrict__ Al,
    const __nv_bfloat16* __restrict__ Wh, const __nv_bfloat16* __restrict__ Wl,
    const float* __restrict__ bias, const float* __restrict__ resid,
    __nv_bfloat16* __restrict__ Oh, __nv_bfloat16* __restrict__ Ol,
    float* __restrict__ Of)
{
    extern __shared__ __align__(16) char smem_raw[];
    const unsigned sb = sptr(smem_raw);
    const int t = threadIdx.x, lane = t & 31, w = t >> 5;
    const int wm = w & 3, wn = w >> 2;
    const int row0 = blockIdx.y * 128, col0 = blockIdx.x * 64;

    float acc[2][4][4] = {};

    gload<SPLIT>(sb, 0, Ah, Al, Wh, Wl, row0, col0, 0, t);
    cp_commit();

    for (int it = 0; it < 16; it++) {
        if (it < 15)
            gload<SPLIT>(sb, (it + 1) & 1, Ah, Al, Wh, Wl, row0, col0, (it + 1) * 32, t);
        cp_commit();
        cp_wait1();
        __syncthreads();

        const unsigned abh = sb + GOff<SPLIT>::AH + (it & 1) * GOff<SPLIT>::ABUF;
        const unsigned abl = sb + GOff<SPLIT>::AL + (it & 1) * GOff<SPLIT>::ABUF;
        const unsigned wbh = sb + GOff<SPLIT>::WH + (it & 1) * GOff<SPLIT>::WBUF;
        const unsigned wbl = sb + GOff<SPLIT>::WL + (it & 1) * GOff<SPLIT>::WBUF;

        #pragma unroll
        for (int k2 = 0; k2 < 32; k2 += 16) {
            unsigned ah[2][4], al[2][4];
            #pragma unroll
            for (int mi = 0; mi < 2; mi++) {
                int r = wm * 32 + mi * 16 + (lane & 15);
                int c = k2 + ((lane >> 4) << 3);
                ldsm4(ah[mi], abh + r * 80 + c * 2);
                if (SPLIT) ldsm4(al[mi], abl + r * 80 + c * 2);
            }
            #pragma unroll
            for (int g = 0; g < 2; g++) {
                int kr = k2 + (lane & 7) + (((lane >> 3) & 1) << 3);
                int nc = wn * 32 + g * 16 + ((lane >> 4) << 3);
                unsigned bh_[4], bl_[4];
                ldsm4t(bh_, wbh + kr * 144 + nc * 2);
                if (SPLIT) ldsm4t(bl_, wbl + kr * 144 + nc * 2);
                #pragma unroll
                for (int mi = 0; mi < 2; mi++) {
                    mma_bf16(acc[mi][2*g],   ah[mi], &bh_[0]);
                    mma_bf16(acc[mi][2*g+1], ah[mi], &bh_[2]);
                    if (SPLIT) {
                        mma_bf16(acc[mi][2*g],   ah[mi], &bl_[0]);
                        mma_bf16(acc[mi][2*g+1], ah[mi], &bl_[2]);
                        mma_bf16(acc[mi][2*g],   al[mi], &bh_[0]);
                        mma_bf16(acc[mi][2*g+1], al[mi], &bh_[2]);
                    }
                }
            }
        }
        __syncthreads();
    }

    #pragma unroll
    for (int mi = 0; mi < 2; mi++) {
        #pragma unroll
        for (int nf = 0; nf < 4; nf++) {
            float* c = acc[mi][nf];
            int m = row0 + wm * 32 + mi * 16 + (lane >> 2);
            int n = col0 + wn * 32 + nf * 8 + ((lane & 3) << 1);
            float b0 = bias[n], b1 = bias[n + 1];
            if (OUTPROJ) {
                float2 r = *(const float2*)(resid + (size_t)m * 512 + n);
                *(float2*)(Of + (size_t)m * 512 + n) =
                    make_float2(c[0] + b0 + r.x, c[1] + b1 + r.y);
                r = *(const float2*)(resid + (size_t)(m + 8) * 512 + n);
                *(float2*)(Of + (size_t)(m + 8) * 512 + n) =
                    make_float2(c[2] + b0 + r.x, c[3] + b1 + r.y);
            } else {
                int h = n >> 6, d = n & 63;
                int b = m >> 11, s = m & 2047;
                size_t base = ((size_t)(b * NH + h) * SS + s) * DK + d;
                if (OUTLO) {
                    __nv_bfloat162 h2, l2;
                    split_pair(c[0] + b0, c[1] + b1, h2, l2);
                    *(__nv_bfloat162*)&Oh[base] = h2;
                    *(__nv_bfloat162*)&Ol[base] = l2;
                    split_pair(c[2] + b0, c[3] + b1, h2, l2);
                    *(__nv_bfloat162*)&Oh[base + 8 * (size_t)DK] = h2;
                    *(__nv_bfloat162*)&Ol[base + 8 * (size_t)DK] = l2;
                } else {
                    *(__nv_bfloat162*)&Oh[base] =
                        __float22bfloat162_rn(make_float2(c[0] + b0, c[1] + b1));
                    *(__nv_bfloat162*)&Oh[base + 8 * (size_t)DK] =
                        __float22bfloat162_rn(make_float2(c[2] + b0, c[3] + b1));
                }
            }
        }
    }
}

// ---------------------------------------------------------------------------
// Context + softmax normalize, pure bf16 P and V (precision budget).
// Reads raw scores, writes probs in-place, ctx = P @ V stored bf16.
// (256,3): split machinery removed -> register footprint fits 80-reg clamp.
// ---------------------------------------------------------------------------
__global__ __launch_bounds__(256, 3) void mma_context(
    float* __restrict__ attn, const float* __restrict__ rowm,
    const float* __restrict__ rinv, __nv_bfloat16* __restrict__ ctxh)
{
    __shared__ __align__(16) __nv_bfloat16 Ph[128][72];
    __shared__ __align__(16) __nv_bfloat16 Vh[64][72];
    const int t = threadIdx.x, lane = t & 31, w = t >> 5;
    const int wm = w & 3, wn = w >> 2;
    const int bh = blockIdx.y, r0 = blockIdx.x * 128;
    const size_t vbase = (size_t)bh * SS * DK;

    const int pr = t >> 1, pc = (t & 1) * 32;
    const float rm = __ldg(rowm + (size_t)bh * SS + r0 + pr);
    const float ri = __ldg(rinv + (size_t)bh * SS + r0 + pr);
    float* prow = attn + (size_t)bh * SS * SS + (size_t)(r0 + pr) * SS + pc;

    float acc[2][4][4] = {};

    for (int kk = 0; kk < SS; kk += 64) {
        {   // V chunk 64x64 bf16: 512 chunks of 16B, 2/thread
            #pragma unroll
            for (int i = 0; i < 2; i++) {
                int idx = t + i * 256;
                int vr = idx >> 3, vc = (idx & 7) * 8;
                cp16(sptr(&Vh[vr][vc]), g_vh + vbase + (size_t)(kk + vr) * 64 + vc);
            }
        }
        {   // P chunk: exp-normalize + write probs + pack bf16
            float* p = prow + kk;
            #pragma unroll
            for (int i = 0; i < 32; i += 4) {
                float4 v = *(float4*)(p + i);
                v.x = __expf(v.x - rm) * ri;
                v.y = __expf(v.y - rm) * ri;
                v.z = __expf(v.z - rm) * ri;
                v.w = __expf(v.w - rm) * ri;
                *(float4*)(p + i) = v;               // final attn probabilities
                *(__nv_bfloat162*)&Ph[pr][pc + i] =
                    __float22bfloat162_rn(make_float2(v.x, v.y));
                *(__nv_bfloat162*)&Ph[pr][pc + i + 2] =
                    __float22bfloat162_rn(make_float2(v.z, v.w));
            }
        }
        cp_commit();
        cp_wait0();
        __syncthreads();
        #pragma unroll
        for (int k2 = 0; k2 < 64; k2 += 16) {
            unsigned ah[2][4];
            #pragma unroll
            for (int mi = 0; mi < 2; mi++) {
                int r = wm * 32 + mi * 16 + (lane & 15);
                int c = k2 + ((lane >> 4) << 3);
                ldsm4(ah[mi], sptr(&Ph[r][c]));
            }
            #pragma unroll
            for (int g = 0; g < 2; g++) {
                int kr = k2 + (lane & 7) + (((lane >> 3) & 1) << 3);
                int nc = wn * 32 + g * 16 + ((lane >> 4) << 3);
                unsigned bh_[4];
                ldsm4t(bh_, sptr(&Vh[kr][nc]));
                #pragma unroll
                for (int mi = 0; mi < 2; mi++) {
                    mma_bf16(acc[mi][2*g],   ah[mi], &bh_[0]);
                    mma_bf16(acc[mi][2*g+1], ah[mi], &bh_[2]);
                }
            }
        }
        __syncthreads();
    }

    const int b = bh >> 3, h = bh & 7;
    #pragma unroll
    for (int mi = 0; mi < 2; mi++) {
        #pragma unroll
        for (int nf = 0; nf < 4; nf++) {
            float* c = acc[mi][nf];
            int m = r0 + wm * 32 + mi * 16 + (lane >> 2);
            int n = wn * 32 + nf * 8 + ((lane & 3) << 1);
            size_t idx = ((size_t)(b * SS + m)) * EMB + h * DK + n;
            *(__nv_bfloat162*)&ctxh[idx] =
                __float22bfloat162_rn(make_float2(c[0], c[1]));
            *(__nv_bfloat162*)&ctxh[idx + 8 * (size_t)EMB] =
                __float22bfloat162_rn(make_float2(c[2], c[3]));
        }
    }
}

// ---------------------------------------------------------------------------
// LayerNorm over 512.
// ---------------------------------------------------------------------------
__global__ __launch_bounds__(128) void ln_kernel(
    const float* __restrict__ gamma, const float* __restrict__ beta,
    float* __restrict__ out)
{
    const size_t row = blockIdx.x;
    const int t = threadIdx.x;
    const float* x = g_x + row * EMB;
    __shared__ float rs[4], rq[4];

    float4 v = ((const float4*)x)[t];
    float s  = v.x + v.y + v.z + v.w;
    float sq = v.x*v.x + v.y*v.y + v.z*v.z + v.w*v.w;
    #pragma unroll
    for (int o = 16; o; o >>= 1) {
        s  += __shfl_xor_sync(0xffffffffu, s,  o);
        sq += __shfl_xor_sync(0xffffffffu, sq, o);
    }
    if ((t & 31) == 0) { rs[t >> 5] = s; rq[t >> 5] = sq; }
    __syncthreads();
    s  = rs[0] + rs[1] + rs[2] + rs[3];
    sq = rq[0] + rq[1] + rq[2] + rq[3];

    float mu  = s * (1.0f / 512.0f);
    float var = sq * (1.0f / 512.0f) - mu * mu;
    float inv = rsqrtf(var + 1e-5f);

    float4 g = ((const float4*)gamma)[t];
    float4 bb = ((const float4*)beta)[t];
    float4 o;
    o.x = (v.x - mu) * inv * g.x + bb.x;
    o.y = (v.y - mu) * inv * g.y + bb.y;
    o.z = (v.z - mu) * inv * g.z + bb.z;
    o.w = (v.w - mu) * inv * g.w + bb.w;
    ((float4*)(out + row * EMB))[t] = o;
}

// ---------------------------------------------------------------------------
extern "C" void kernel_launch(void* const* d_in, const int* in_sizes, int n_in,
                              void* d_out, int out_size)
{
    const float* Q  = (const float*)d_in[0];
    const float* K  = (const float*)d_in[1];
    const float* V  = (const float*)d_in[2];
    const unsigned char* mask = (const unsigned char*)d_in[3];
    const float* Wq = (const float*)d_in[4];
    const float* bq = (const float*)d_in[5];
    const float* Wk = (const float*)d_in[6];
    const float* bk = (const float*)d_in[7];
    const float* Wv = (const float*)d_in[8];
    const float* bv = (const float*)d_in[9];
    const float* Wo = (const float*)d_in[10];
    const float* bo = (const float*)d_in[11];
    const float* gamma = (const float*)d_in[12];
    const float* beta  = (const float*)d_in[13];

    float* out  = (float*)d_out;
    float* attn = out + (size_t)BSROWS * EMB;

    __nv_bfloat16 *qh, *ql, *kh, *kl, *vh;
    __nv_bfloat16 *inqh, *inql, *inkh, *inkl, *invh;
    __nv_bfloat16 *wqh, *wql, *wkh, *wkl, *wvh, *woh;
    __nv_bfloat16 *ctxh;
    float *xp, *rowmp, *rinvp;
    cudaGetSymbolAddress((void**)&qh, g_qh);
    cudaGetSymbolAddress((void**)&ql, g_ql);
    cudaGetSymbolAddress((void**)&kh, g_kh);
    cudaGetSymbolAddress((void**)&kl, g_kl);
    cudaGetSymbolAddress((void**)&vh, g_vh);
    cudaGetSymbolAddress((void**)&inqh, g_inqh);
    cudaGetSymbolAddress((void**)&inql, g_inql);
    cudaGetSymbolAddress((void**)&inkh, g_inkh);
    cudaGetSymbolAddress((void**)&inkl, g_inkl);
    cudaGetSymbolAddress((void**)&invh, g_invh);
    cudaGetSymbolAddress((void**)&wqh, g_wqh);
    cudaGetSymbolAddress((void**)&wql, g_wql);
    cudaGetSymbolAddress((void**)&wkh, g_wkh);
    cudaGetSymbolAddress((void**)&wkl, g_wkl);
    cudaGetSymbolAddress((void**)&wvh, g_wvh);
    cudaGetSymbolAddress((void**)&woh, g_woh);
    cudaGetSymbolAddress((void**)&ctxh, g_ctxh);
    cudaGetSymbolAddress((void**)&xp,   g_x);
    cudaGetSymbolAddress((void**)&rowmp, g_rowm);
    cudaGetSymbolAddress((void**)&rinvp, g_rinv);

    cudaFuncSetAttribute(mma_scores, cudaFuncAttributeMaxDynamicSharedMemorySize,
                         SC_SMEM);
    cudaFuncSetAttribute(mma_gemm512<0,1,1>, cudaFuncAttributeMaxDynamicSharedMemorySize,
                         GOff<1>::SMEM);
    cudaFuncSetAttribute(mma_gemm512<0,0,0>, cudaFuncAttributeMaxDynamicSharedMemorySize,
                         GOff<0>::SMEM);
    cudaFuncSetAttribute(mma_gemm512<1,0,0>, cudaFuncAttributeMaxDynamicSharedMemorySize,
                         GOff<0>::SMEM);

    // batched conversions
    const int n4_in = BSROWS * EMB / 4;       // 1,048,576
    const int n4_w  = EMB * EMB / 4;          // 65,536
    split_inputs<<<(n4_in * 3 + 255) / 256, 256>>>(Q, K, V, n4_in);
    split_weights<<<(n4_w * 4 + 255) / 256, 256>>>(Wq, Wk, Wv, Wo, n4_w);

    dim3 gemm_grid(EMB / 64, BSROWS / 128);        // 8 x 64
    mma_gemm512<0,1,1><<<gemm_grid, 256, GOff<1>::SMEM>>>(
        inqh, inql, wqh, wql, bq, nullptr, qh, ql, nullptr);
    mma_gemm512<0,1,1><<<gemm_grid, 256, GOff<1>::SMEM>>>(
        inkh, inkl, wkh, wkl, bk, nullptr, kh, kl, nullptr);
    mma_gemm512<0,0,0><<<gemm_grid, 256, GOff<0>::SMEM>>>(
        invh, nullptr, wvh, nullptr, bv, nullptr, vh, nullptr, nullptr);

    dim3 sc_grid(SS / 64, SS / 128, BH);           // 32 x 16 x 32
    mma_scores<<<sc_grid, 256, SC_SMEM>>>(mask, attn);

    softmax_stats<<<(BH * SS) / 8, 256>>>(rowmp, rinvp);

    dim3 ctx_grid(SS / 128, BH);                   // 16 x 32
    mma_context<<<ctx_grid, 256>>>(attn, rowmp, rinvp, ctxh);

    mma_gemm512<1,0,0><<<gemm_grid, 256, GOff<0>::SMEM>>>(
        ctxh, nullptr, woh, nullptr, bo, Q, nullptr, nullptr, xp);

    ln_kernel<<<BSROWS, 128>>>(gamma, beta, out);
}

// round 12
// speedup vs baseline: 1.3036x; 1.3036x over previous
#include <cuda_runtime.h>
#include <cuda_bf16.h>
#include <math.h>

#define BB   4
#define SS   2048
#define EMB  512
#define NH   8
#define DK   64
#define BSROWS (BB*SS)   // 8192
#define BH   (BB*NH)     // 32
#define NCT  (SS/64)     // 32 col tiles in scores

// projection outputs
__device__ __nv_bfloat16 g_qh[BH * SS * DK];
__device__ __nv_bfloat16 g_ql[BH * SS * DK];
__device__ __nv_bfloat16 g_kh[BH * SS * DK];
__device__ __nv_bfloat16 g_kl[BH * SS * DK];
__device__ __nv_bfloat16 g_vh[BH * SS * DK];       // plain bf16 (precision budget)
// pre-split / pre-converted inputs
__device__ __nv_bfloat16 g_inqh[BSROWS * EMB], g_inql[BSROWS * EMB];
__device__ __nv_bfloat16 g_inkh[BSROWS * EMB], g_inkl[BSROWS * EMB];
__device__ __nv_bfloat16 g_invh[BSROWS * EMB];
// weights
__device__ __nv_bfloat16 g_wqh[EMB * EMB], g_wql[EMB * EMB];
__device__ __nv_bfloat16 g_wkh[EMB * EMB], g_wkl[EMB * EMB];
__device__ __nv_bfloat16 g_wvh[EMB * EMB];
__device__ __nv_bfloat16 g_woh[EMB * EMB];
// context (plain bf16) + pre-LN sum
__device__ __nv_bfloat16 g_ctxh[BSROWS * EMB];
__device__ float g_x[BSROWS * EMB];
// softmax stats
__device__ float g_smax[(size_t)BH * SS * NCT];
__device__ float g_ssum[(size_t)BH * SS * NCT];
__device__ float g_rowm[(size_t)BH * SS];
__device__ float g_rinv[(size_t)BH * SS];

// ---------------------------------------------------------------------------
// helpers
// ---------------------------------------------------------------------------
__device__ __forceinline__ unsigned sptr(const void* p) {
    return (unsigned)__cvta_generic_to_shared(p);
}
__device__ __forceinline__ void ldsm4(unsigned* r, unsigned a) {
    asm volatile("ldmatrix.sync.aligned.m8n8.x4.shared.b16 {%0,%1,%2,%3}, [%4];"
                 : "=r"(r[0]), "=r"(r[1]), "=r"(r[2]), "=r"(r[3]) : "r"(a));
}
__device__ __forceinline__ void ldsm4t(unsigned* r, unsigned a) {
    asm volatile("ldmatrix.sync.aligned.m8n8.x4.trans.shared.b16 {%0,%1,%2,%3}, [%4];"
                 : "=r"(r[0]), "=r"(r[1]), "=r"(r[2]), "=r"(r[3]) : "r"(a));
}
__device__ __forceinline__ void mma_bf16(float* c, const unsigned* a, const unsigned* b) {
    asm volatile(
        "mma.sync.aligned.m16n8k16.row.col.f32.bf16.bf16.f32 "
        "{%0,%1,%2,%3},{%4,%5,%6,%7},{%8,%9},{%0,%1,%2,%3};"
        : "+f"(c[0]), "+f"(c[1]), "+f"(c[2]), "+f"(c[3])
        : "r"(a[0]), "r"(a[1]), "r"(a[2]), "r"(a[3]), "r"(b[0]), "r"(b[1]));
}
__device__ __forceinline__ void split_pair(float x, float y,
                                           __nv_bfloat162& h2, __nv_bfloat162& l2) {
    __nv_bfloat16 hx = __float2bfloat16_rn(x);
    __nv_bfloat16 hy = __float2bfloat16_rn(y);
    __nv_bfloat16 lx = __float2bfloat16_rn(x - __bfloat162float(hx));
    __nv_bfloat16 ly = __float2bfloat16_rn(y - __bfloat162float(hy));
    h2 = __halves2bfloat162(hx, hy);
    l2 = __halves2bfloat162(lx, ly);
}
__device__ __forceinline__ void cp16(unsigned dst, const void* src) {
    asm volatile("cp.async.cg.shared.global [%0], [%1], 16;" :: "r"(dst), "l"(src));
}
__device__ __forceinline__ void cp_commit() {
    asm volatile("cp.async.commit_group;");
}
__device__ __forceinline__ void cp_wait0() {
    asm volatile("cp.async.wait_group 0;");
}
__device__ __forceinline__ void cp_wait1() {
    asm volatile("cp.async.wait_group 1;");
}

// ---------------------------------------------------------------------------
// Batched conversions: Q,K -> hi/lo, V -> hi; Wq,Wk -> hi/lo, Wv,Wo -> hi.
// ---------------------------------------------------------------------------
__global__ __launch_bounds__(256) void split_inputs(
    const float* __restrict__ Q, const float* __restrict__ K,
    const float* __restrict__ V, int n4)
{
    int i = blockIdx.x * blockDim.x + threadIdx.x;
    if (i >= n4 * 3) return;
    int which = i / n4, j = i - which * n4;
    const float* in = which == 0 ? Q : which == 1 ? K : V;
    float4 v = ((const float4*)in)[j];
    __nv_bfloat162 h2, l2, h3, l3;
    split_pair(v.x, v.y, h2, l2);
    split_pair(v.z, v.w, h3, l3);
    __nv_bfloat16* hi = which == 0 ? g_inqh : which == 1 ? g_inkh : g_invh;
    ((__nv_bfloat162*)hi)[j * 2]     = h2;
    ((__nv_bfloat162*)hi)[j * 2 + 1] = h3;
    if (which < 2) {
        __nv_bfloat16* lo = which == 0 ? g_inql : g_inkl;
        ((__nv_bfloat162*)lo)[j * 2]     = l2;
        ((__nv_bfloat162*)lo)[j * 2 + 1] = l3;
    }
}

__global__ __launch_bounds__(256) void split_weights(
    const float* __restrict__ Wq, const float* __restrict__ Wk,
    const float* __restrict__ Wv, const float* __restrict__ Wo, int n4)
{
    int i = blockIdx.x * blockDim.x + threadIdx.x;
    if (i >= n4 * 4) return;
    int which = i / n4, j = i - which * n4;
    const float* in = which == 0 ? Wq : which == 1 ? Wk : which == 2 ? Wv : Wo;
    float4 v = ((const float4*)in)[j];
    __nv_bfloat162 h2, l2, h3, l3;
    split_pair(v.x, v.y, h2, l2);
    split_pair(v.z, v.w, h3, l3);
    __nv_bfloat16* hi = which == 0 ? g_wqh : which == 1 ? g_wkh
                      : which == 2 ? g_wvh : g_woh;
    ((__nv_bfloat162*)hi)[j * 2]     = h2;
    ((__nv_bfloat162*)hi)[j * 2 + 1] = h3;
    if (which < 2) {
        __nv_bfloat16* lo = which == 0 ? g_wql : g_wkl;
        ((__nv_bfloat162*)lo)[j * 2]     = l2;
        ((__nv_bfloat162*)lo)[j * 2 + 1] = l3;
    }
}

// ---------------------------------------------------------------------------
// Scores: per (b,h) 128x64 tile of q @ k^T * 0.125, masked, fp32 to attn.
// Split (3-product) MMA; coalesced smem-restaged epilogue + row stats.
// ---------------------------------------------------------------------------
#define SC_QH 0
#define SC_QL 18432
#define SC_KH 36864
#define SC_KL 46080
#define SC_SMEM 55296

__global__ __launch_bounds__(256, 3) void mma_scores(
    const unsigned char* __restrict__ mask, float* __restrict__ attn)
{
    extern __shared__ __align__(16) char smem_raw[];
    __nv_bfloat16 (*Qh)[72] = (__nv_bfloat16(*)[72])(smem_raw + SC_QH);
    __nv_bfloat16 (*Ql)[72] = (__nv_bfloat16(*)[72])(smem_raw + SC_QL);
    __nv_bfloat16 (*Kh)[72] = (__nv_bfloat16(*)[72])(smem_raw + SC_KH);
    __nv_bfloat16 (*Kl)[72] = (__nv_bfloat16(*)[72])(smem_raw + SC_KL);

    const int t = threadIdx.x, lane = t & 31, w = t >> 5;
    const int wm = w & 3, wn = w >> 2;
    const int bh = blockIdx.z, b = bh >> 3;
    const int r0 = blockIdx.y * 128, c0 = blockIdx.x * 64;
    const size_t base = (size_t)bh * SS * DK;

    #pragma unroll
    for (int i = 0; i < 12; i++) {
        int ch = t + i * 256;
        if (ch < 1024) {
            int r = ch >> 3, c8 = (ch & 7) * 8;
            cp16(sptr(&Qh[r][c8]), g_qh + base + (size_t)(r0 + r) * 64 + c8);
        } else if (ch < 2048) {
            int idx = ch - 1024, r = idx >> 3, c8 = (idx & 7) * 8;
            cp16(sptr(&Ql[r][c8]), g_ql + base + (size_t)(r0 + r) * 64 + c8);
        } else if (ch < 2560) {
            int idx = ch - 2048, r = idx >> 3, c8 = (idx & 7) * 8;
            cp16(sptr(&Kh[r][c8]), g_kh + base + (size_t)(c0 + r) * 64 + c8);
        } else {
            int idx = ch - 2560, r = idx >> 3, c8 = (idx & 7) * 8;
            cp16(sptr(&Kl[r][c8]), g_kl + base + (size_t)(c0 + r) * 64 + c8);
        }
    }
    cp_commit();
    cp_wait0();
    __syncthreads();

    float acc[2][4][4] = {};
    #pragma unroll
    for (int k2 = 0; k2 < 64; k2 += 16) {
        unsigned ah[2][4], al[2][4];
        #pragma unroll
        for (int mi = 0; mi < 2; mi++) {
            int r = wm * 32 + mi * 16 + (lane & 15);
            int c = k2 + ((lane >> 4) << 3);
            ldsm4(ah[mi], sptr(&Qh[r][c]));
            ldsm4(al[mi], sptr(&Ql[r][c]));
        }
        #pragma unroll
        for (int g = 0; g < 2; g++) {
            int nr = wn * 32 + g * 16 + (lane & 7) + ((lane >> 4) << 3);
            int kc = k2 + (((lane >> 3) & 1) << 3);
            unsigned bh_[4], bl_[4];
            ldsm4(bh_, sptr(&Kh[nr][kc]));
            ldsm4(bl_, sptr(&Kl[nr][kc]));
            #pragma unroll
            for (int mi = 0; mi < 2; mi++) {
                mma_bf16(acc[mi][2*g],   ah[mi], &bh_[0]);
                mma_bf16(acc[mi][2*g+1], ah[mi], &bh_[2]);
                mma_bf16(acc[mi][2*g],   ah[mi], &bl_[0]);
                mma_bf16(acc[mi][2*g+1], ah[mi], &bl_[2]);
                mma_bf16(acc[mi][2*g],   al[mi], &bh_[0]);
                mma_bf16(acc[mi][2*g+1], al[mi], &bh_[2]);
            }
        }
    }

    // restage through smem: [128][68] fp32, halves at col offsets 0/34
    __syncthreads();
    float* stg = (float*)smem_raw;
    #pragma unroll
    for (int mi = 0; mi < 2; mi++) {
        #pragma unroll
        for (int nf = 0; nf < 4; nf++) {
            float* c = acc[mi][nf];
            int r = wm * 32 + mi * 16 + (lane >> 2);
            int cc = wn * 34 + nf * 8 + (lane & 3) * 2;
            *(float2*)&stg[r * 68 + cc]       = make_float2(c[0], c[1]);
            *(float2*)&stg[(r + 8) * 68 + cc] = make_float2(c[2], c[3]);
        }
    }
    __syncthreads();

    {
        const int colg = lane * 2;
        const int colp = colg + (lane >= 16 ? 2 : 0);
        #pragma unroll 4
        for (int r = 0; r < 16; r++) {
            int row = w * 16 + r;
            float2 v = *(float2*)&stg[row * 68 + colp];
            size_t gr = (size_t)(r0 + row);
            const unsigned char* mp = mask + ((size_t)b * SS + gr) * SS + c0 + colg;
            v.x = mp[0] ? -1e9f : v.x * 0.125f;
            v.y = mp[1] ? -1e9f : v.y * 0.125f;
            *(float2*)(attn + ((size_t)bh * SS + gr) * SS + c0 + colg) = v;
            float mx = fmaxf(v.x, v.y);
            #pragma unroll
            for (int o = 16; o; o >>= 1) mx = fmaxf(mx, __shfl_xor_sync(0xffffffffu, mx, o));
            float s = __expf(v.x - mx) + __expf(v.y - mx);
            #pragma unroll
            for (int o = 16; o; o >>= 1) s += __shfl_xor_sync(0xffffffffu, s, o);
            if (lane == 0) {
                size_t idx = ((size_t)bh * SS + gr) * NCT + blockIdx.x;
                g_smax[idx] = mx;
                g_ssum[idx] = s;
            }
        }
    }
}

// ---------------------------------------------------------------------------
// Combine tile stats into per-row max and 1/sum. One warp per row.
// ---------------------------------------------------------------------------
__global__ __launch_bounds__(256) void softmax_stats(
    float* __restrict__ rowm, float* __restrict__ rinv)
{
    const int w = threadIdx.x >> 5, lane = threadIdx.x & 31;
    const size_t rg = (size_t)blockIdx.x * 8 + w;
    float m_l = g_smax[rg * NCT + lane];
    float s_l = g_ssum[rg * NCT + lane];
    float m = m_l;
    #pragma unroll
    for (int o = 16; o; o >>= 1) m = fmaxf(m, __shfl_xor_sync(0xffffffffu, m, o));
    float c = __expf(m_l - m) * s_l;
    #pragma unroll
    for (int o = 16; o; o >>= 1) c += __shfl_xor_sync(0xffffffffu, c, o);
    if (lane == 0) { rowm[rg] = m; rinv[rg] = 1.0f / c; }
}

// ---------------------------------------------------------------------------
// GEMM: C = A[M,512] @ W[512,512] + bias (+resid). Block 128x64, 256 thr,
// double-buffered cp.async. SPLIT=1: 3-product hi/lo; SPLIT=0: plain bf16.
// ---------------------------------------------------------------------------
template<int SPLIT>
struct GOff {
    static const unsigned AH = 0;
    static const unsigned AL = 20480;
    static const unsigned WH = SPLIT ? 40960u : 20480u;
    static const unsigned WL = 50176;
    static const unsigned ABUF = 10240;
    static const unsigned WBUF = 4608;
    static const unsigned SMEM = SPLIT ? 59392u : 29696u;
};

template<int SPLIT>
__device__ __forceinline__ void gload(
    unsigned sb, int buf,
    const __nv_bfloat16* __restrict__ Ah, const __nv_bfloat16* __restrict__ Al,
    const __nv_bfloat16* __restrict__ Wh, const __nv_bfloat16* __restrict__ Wl,
    int row0, int col0, int kk, int t)
{
    #pragma unroll
    for (int i = 0; i < 2; i++) {
        int ch = t + i * 256;
        int r = ch >> 2, c = (ch & 3) * 8;
        unsigned off = buf * GOff<SPLIT>::ABUF + r * 80 + c * 2;
        cp16(sb + GOff<SPLIT>::AH + off, Ah + (size_t)(row0 + r) * 512 + kk + c);
        if (SPLIT)
            cp16(sb + GOff<SPLIT>::AL + off, Al + (size_t)(row0 + r) * 512 + kk + c);
    }
    {
        int r = t >> 3, c = (t & 7) * 8;
        unsigned off = buf * GOff<SPLIT>::WBUF + r * 144 + c * 2;
        cp16(sb + GOff<SPLIT>::WH + off, Wh + (size_t)(kk + r) * 512 + col0 + c);
        if (SPLIT)
            cp16(sb + GOff<SPLIT>::WL + off, Wl + (size_t)(kk + r) * 512 + col0 + c);
    }
}

template<int OUTPROJ, int SPLIT, int OUTLO>
__global__ __launch_bounds__(256, 3) void mma_gemm512(
    const __nv_bfloat16* __restrict__ Ah, const __nv_bfloat16* __restrict__ Al,
    const __nv_bfloat16* __restrict__ Wh, const __nv_bfloat16* __restrict__ Wl,
    const float* __restrict__ bias, const float* __restrict__ resid,
    __nv_bfloat16* __restrict__ Oh, __nv_bfloat16* __restrict__ Ol,
    float* __restrict__ Of)
{
    extern __shared__ __align__(16) char smem_raw[];
    const unsigned sb = sptr(smem_raw);
    const int t = threadIdx.x, lane = t & 31, w = t >> 5;
    const int wm = w & 3, wn = w >> 2;
    const int row0 = blockIdx.y * 128, col0 = blockIdx.x * 64;

    float acc[2][4][4] = {};

    gload<SPLIT>(sb, 0, Ah, Al, Wh, Wl, row0, col0, 0, t);
    cp_commit();

    for (int it = 0; it < 16; it++) {
        if (it < 15)
            gload<SPLIT>(sb, (it + 1) & 1, Ah, Al, Wh, Wl, row0, col0, (it + 1) * 32, t);
        cp_commit();
        cp_wait1();
        __syncthreads();

        const unsigned abh = sb + GOff<SPLIT>::AH + (it & 1) * GOff<SPLIT>::ABUF;
        const unsigned abl = sb + GOff<SPLIT>::AL + (it & 1) * GOff<SPLIT>::ABUF;
        const unsigned wbh = sb + GOff<SPLIT>::WH + (it & 1) * GOff<SPLIT>::WBUF;
        const unsigned wbl = sb + GOff<SPLIT>::WL + (it & 1) * GOff<SPLIT>::WBUF;

        #pragma unroll
        for (int k2 = 0; k2 < 32; k2 += 16) {
            unsigned ah[2][4], al[2][4];
            #pragma unroll
            for (int mi = 0; mi < 2; mi++) {
                int r = wm * 32 + mi * 16 + (lane & 15);
                int c = k2 + ((lane >> 4) << 3);
                ldsm4(ah[mi], abh + r * 80 + c * 2);
                if (SPLIT) ldsm4(al[mi], abl + r * 80 + c * 2);
            }
            #pragma unroll
            for (int g = 0; g < 2; g++) {
                int kr = k2 + (lane & 7) + (((lane >> 3) & 1) << 3);
                int nc = wn * 32 + g * 16 + ((lane >> 4) << 3);
                unsigned bh_[4], bl_[4];
                ldsm4t(bh_, wbh + kr * 144 + nc * 2);
                if (SPLIT) ldsm4t(bl_, wbl + kr * 144 + nc * 2);
                #pragma unroll
                for (int mi = 0; mi < 2; mi++) {
                    mma_bf16(acc[mi][2*g],   ah[mi], &bh_[0]);
                    mma_bf16(acc[mi][2*g+1], ah[mi], &bh_[2]);
                    if (SPLIT) {
                        mma_bf16(acc[mi][2*g],   ah[mi], &bl_[0]);
                        mma_bf16(acc[mi][2*g+1], ah[mi], &bl_[2]);
                        mma_bf16(acc[mi][2*g],   al[mi], &bh_[0]);
                        mma_bf16(acc[mi][2*g+1], al[mi], &bh_[2]);
                    }
                }
            }
        }
        __syncthreads();
    }

    #pragma unroll
    for (int mi = 0; mi < 2; mi++) {
        #pragma unroll
        for (int nf = 0; nf < 4; nf++) {
            float* c = acc[mi][nf];
            int m = row0 + wm * 32 + mi * 16 + (lane >> 2);
            int n = col0 + wn * 32 + nf * 8 + ((lane & 3) << 1);
            float b0 = bias[n], b1 = bias[n + 1];
            if (OUTPROJ) {
                float2 r = *(const float2*)(resid + (size_t)m * 512 + n);
                *(float2*)(Of + (size_t)m * 512 + n) =
                    make_float2(c[0] + b0 + r.x, c[1] + b1 + r.y);
                r = *(const float2*)(resid + (size_t)(m + 8) * 512 + n);
                *(float2*)(Of + (size_t)(m + 8) * 512 + n) =
                    make_float2(c[2] + b0 + r.x, c[3] + b1 + r.y);
            } else {
                int h = n >> 6, d = n & 63;
                int b = m >> 11, s = m & 2047;
                size_t base = ((size_t)(b * NH + h) * SS + s) * DK + d;
                if (OUTLO) {
                    __nv_bfloat162 h2, l2;
                    split_pair(c[0] + b0, c[1] + b1, h2, l2);
                    *(__nv_bfloat162*)&Oh[base] = h2;
                    *(__nv_bfloat162*)&Ol[base] = l2;
                    split_pair(c[2] + b0, c[3] + b1, h2, l2);
                    *(__nv_bfloat162*)&Oh[base + 8 * (size_t)DK] = h2;
                    *(__nv_bfloat162*)&Ol[base + 8 * (size_t)DK] = l2;
                } else {
                    *(__nv_bfloat162*)&Oh[base] =
                        __float22bfloat162_rn(make_float2(c[0] + b0, c[1] + b1));
                    *(__nv_bfloat162*)&Oh[base + 8 * (size_t)DK] =
                        __float22bfloat162_rn(make_float2(c[2] + b0, c[3] + b1));
                }
            }
        }
    }
}

// ---------------------------------------------------------------------------
// Context + softmax normalize, pure bf16 P and V (precision budget).
// Reads raw scores, writes probs in-place, ctx = P @ V stored bf16.
// (256,2) ONLY: the 80-reg (256,3) clamp spills the fused exp loop —
// verified twice (rounds 6 and 11, +250..+1700us each time). Do not retry.
// ---------------------------------------------------------------------------
__global__ __launch_bounds__(256, 2) void mma_context(
    float* __restrict__ attn, const float* __restrict__ rowm,
    const float* __restrict__ rinv, __nv_bfloat16* __restrict__ ctxh)
{
    __shared__ __align__(16) __nv_bfloat16 Ph[128][72];
    __shared__ __align__(16) __nv_bfloat16 Vh[64][72];
    const int t = threadIdx.x, lane = t & 31, w = t >> 5;
    const int wm = w & 3, wn = w >> 2;
    const int bh = blockIdx.y, r0 = blockIdx.x * 128;
    const size_t vbase = (size_t)bh * SS * DK;

    const int pr = t >> 1, pc = (t & 1) * 32;
    const float rm = __ldg(rowm + (size_t)bh * SS + r0 + pr);
    const float ri = __ldg(rinv + (size_t)bh * SS + r0 + pr);
    float* prow = attn + (size_t)bh * SS * SS + (size_t)(r0 + pr) * SS + pc;

    float acc[2][4][4] = {};

    for (int kk = 0; kk < SS; kk += 64) {
        {   // V chunk 64x64 bf16: 512 chunks of 16B, 2/thread
            #pragma unroll
            for (int i = 0; i < 2; i++) {
                int idx = t + i * 256;
                int vr = idx >> 3, vc = (idx & 7) * 8;
                cp16(sptr(&Vh[vr][vc]), g_vh + vbase + (size_t)(kk + vr) * 64 + vc);
            }
        }
        {   // P chunk: exp-normalize + write probs + pack bf16
            float* p = prow + kk;
            #pragma unroll
            for (int i = 0; i < 32; i += 4) {
                float4 v = *(float4*)(p + i);
                v.x = __expf(v.x - rm) * ri;
                v.y = __expf(v.y - rm) * ri;
                v.z = __expf(v.z - rm) * ri;
                v.w = __expf(v.w - rm) * ri;
                *(float4*)(p + i) = v;               // final attn probabilities
                *(__nv_bfloat162*)&Ph[pr][pc + i] =
                    __float22bfloat162_rn(make_float2(v.x, v.y));
                *(__nv_bfloat162*)&Ph[pr][pc + i + 2] =
                    __float22bfloat162_rn(make_float2(v.z, v.w));
            }
        }
        cp_commit();
        cp_wait0();
        __syncthreads();
        #pragma unroll
        for (int k2 = 0; k2 < 64; k2 += 16) {
            unsigned ah[2][4];
            #pragma unroll
            for (int mi = 0; mi < 2; mi++) {
                int r = wm * 32 + mi * 16 + (lane & 15);
                int c = k2 + ((lane >> 4) << 3);
                ldsm4(ah[mi], sptr(&Ph[r][c]));
            }
            #pragma unroll
            for (int g = 0; g < 2; g++) {
                int kr = k2 + (lane & 7) + (((lane >> 3) & 1) << 3);
                int nc = wn * 32 + g * 16 + ((lane >> 4) << 3);
                unsigned bh_[4];
                ldsm4t(bh_, sptr(&Vh[kr][nc]));
                #pragma unroll
                for (int mi = 0; mi < 2; mi++) {
                    mma_bf16(acc[mi][2*g],   ah[mi], &bh_[0]);
                    mma_bf16(acc[mi][2*g+1], ah[mi], &bh_[2]);
                }
            }
        }
        __syncthreads();
    }

    const int b = bh >> 3, h = bh & 7;
    #pragma unroll
    for (int mi = 0; mi < 2; mi++) {
        #pragma unroll
        for (int nf = 0; nf < 4; nf++) {
            float* c = acc[mi][nf];
            int m = r0 + wm * 32 + mi * 16 + (lane >> 2);
            int n = wn * 32 + nf * 8 + ((lane & 3) << 1);
            size_t idx = ((size_t)(b * SS + m)) * EMB + h * DK + n;
            *(__nv_bfloat162*)&ctxh[idx] =
                __float22bfloat162_rn(make_float2(c[0], c[1]));
            *(__nv_bfloat162*)&ctxh[idx + 8 * (size_t)EMB] =
                __float22bfloat162_rn(make_float2(c[2], c[3]));
        }
    }
}

// ---------------------------------------------------------------------------
// LayerNorm over 512.
// ---------------------------------------------------------------------------
__global__ __launch_bounds__(128) void ln_kernel(
    const float* __restrict__ gamma, const float* __restrict__ beta,
    float* __restrict__ out)
{
    const size_t row = blockIdx.x;
    const int t = threadIdx.x;
    const float* x = g_x + row * EMB;
    __shared__ float rs[4], rq[4];

    float4 v = ((const float4*)x)[t];
    float s  = v.x + v.y + v.z + v.w;
    float sq = v.x*v.x + v.y*v.y + v.z*v.z + v.w*v.w;
    #pragma unroll
    for (int o = 16; o; o >>= 1) {
        s  += __shfl_xor_sync(0xffffffffu, s,  o);
        sq += __shfl_xor_sync(0xffffffffu, sq, o);
    }
    if ((t & 31) == 0) { rs[t >> 5] = s; rq[t >> 5] = sq; }
    __syncthreads();
    s  = rs[0] + rs[1] + rs[2] + rs[3];
    sq = rq[0] + rq[1] + rq[2] + rq[3];

    float mu  = s * (1.0f / 512.0f);
    float var = sq * (1.0f / 512.0f) - mu * mu;
    float inv = rsqrtf(var + 1e-5f);

    float4 g = ((const float4*)gamma)[t];
    float4 bb = ((const float4*)beta)[t];
    float4 o;
    o.x = (v.x - mu) * inv * g.x + bb.x;
    o.y = (v.y - mu) * inv * g.y + bb.y;
    o.z = (v.z - mu) * inv * g.z + bb.z;
    o.w = (v.w - mu) * inv * g.w + bb.w;
    ((float4*)(out + row * EMB))[t] = o;
}

// ---------------------------------------------------------------------------
extern "C" void kernel_launch(void* const* d_in, const int* in_sizes, int n_in,
                              void* d_out, int out_size)
{
    const float* Q  = (const float*)d_in[0];
    const float* K  = (const float*)d_in[1];
    const float* V  = (const float*)d_in[2];
    const unsigned char* mask = (const unsigned char*)d_in[3];
    const float* Wq = (const float*)d_in[4];
    const float* bq = (const float*)d_in[5];
    const float* Wk = (const float*)d_in[6];
    const float* bk = (const float*)d_in[7];
    const float* Wv = (const float*)d_in[8];
    const float* bv = (const float*)d_in[9];
    const float* Wo = (const float*)d_in[10];
    const float* bo = (const float*)d_in[11];
    const float* gamma = (const float*)d_in[12];
    const float* beta  = (const float*)d_in[13];

    float* out  = (float*)d_out;
    float* attn = out + (size_t)BSROWS * EMB;

    __nv_bfloat16 *qh, *ql, *kh, *kl, *vh;
    __nv_bfloat16 *inqh, *inql, *inkh, *inkl, *invh;
    __nv_bfloat16 *wqh, *wql, *wkh, *wkl, *wvh, *woh;
    __nv_bfloat16 *ctxh;
    float *xp, *rowmp, *rinvp;
    cudaGetSymbolAddress((void**)&qh, g_qh);
    cudaGetSymbolAddress((void**)&ql, g_ql);
    cudaGetSymbolAddress((void**)&kh, g_kh);
    cudaGetSymbolAddress((void**)&kl, g_kl);
    cudaGetSymbolAddress((void**)&vh, g_vh);
    cudaGetSymbolAddress((void**)&inqh, g_inqh);
    cudaGetSymbolAddress((void**)&inql, g_inql);
    cudaGetSymbolAddress((void**)&inkh, g_inkh);
    cudaGetSymbolAddress((void**)&inkl, g_inkl);
    cudaGetSymbolAddress((void**)&invh, g_invh);
    cudaGetSymbolAddress((void**)&wqh, g_wqh);
    cudaGetSymbolAddress((void**)&wql, g_wql);
    cudaGetSymbolAddress((void**)&wkh, g_wkh);
    cudaGetSymbolAddress((void**)&wkl, g_wkl);
    cudaGetSymbolAddress((void**)&wvh, g_wvh);
    cudaGetSymbolAddress((void**)&woh, g_woh);
    cudaGetSymbolAddress((void**)&ctxh, g_ctxh);
    cudaGetSymbolAddress((void**)&xp,   g_x);
    cudaGetSymbolAddress((void**)&rowmp, g_rowm);
    cudaGetSymbolAddress((void**)&rinvp, g_rinv);

    cudaFuncSetAttribute(mma_scores, cudaFuncAttributeMaxDynamicSharedMemorySize,
                         SC_SMEM);
    cudaFuncSetAttribute(mma_gemm512<0,1,1>, cudaFuncAttributeMaxDynamicSharedMemorySize,
                         GOff<1>::SMEM);
    cudaFuncSetAttribute(mma_gemm512<0,0,0>, cudaFuncAttributeMaxDynamicSharedMemorySize,
                         GOff<0>::SMEM);
    cudaFuncSetAttribute(mma_gemm512<1,0,0>, cudaFuncAttributeMaxDynamicSharedMemorySize,
                         GOff<0>::SMEM);

    // batched conversions
    const int n4_in = BSROWS * EMB / 4;       // 1,048,576
    const int n4_w  = EMB * EMB / 4;          // 65,536
    split_inputs<<<(n4_in * 3 + 255) / 256, 256>>>(Q, K, V, n4_in);
    split_weights<<<(n4_w * 4 + 255) / 256, 256>>>(Wq, Wk, Wv, Wo, n4_w);

    dim3 gemm_grid(EMB / 64, BSROWS / 128);        // 8 x 64
    mma_gemm512<0,1,1><<<gemm_grid, 256, GOff<1>::SMEM>>>(
        inqh, inql, wqh, wql, bq, nullptr, qh, ql, nullptr);
    mma_gemm512<0,1,1><<<gemm_grid, 256, GOff<1>::SMEM>>>(
        inkh, inkl, wkh, wkl, bk, nullptr, kh, kl, nullptr);
    mma_gemm512<0,0,0><<<gemm_grid, 256, GOff<0>::SMEM>>>(
        invh, nullptr, wvh, nullptr, bv, nullptr, vh, nullptr, nullptr);

    dim3 sc_grid(SS / 64, SS / 128, BH);           // 32 x 16 x 32
    mma_scores<<<sc_grid, 256, SC_SMEM>>>(mask, attn);

    softmax_stats<<<(BH * SS) / 8, 256>>>(rowmp, rinvp);

    dim3 ctx_grid(SS / 128, BH);                   // 16 x 32
    mma_context<<<ctx_grid, 256>>>(attn, rowmp, rinvp, ctxh);

    mma_gemm512<1,0,0><<<gemm_grid, 256, GOff<0>::SMEM>>>(
        ctxh, nullptr, woh, nullptr, bo, Q, nullptr, nullptr, xp);

    ln_kernel<<<BSROWS, 128>>>(gamma, beta, out);
}

// round 13
// speedup vs baseline: 1.3941x; 1.0694x over previous
#include <cuda_runtime.h>
#include <cuda_bf16.h>
#include <math.h>

#define BB   4
#define SS   2048
#define EMB  512
#define NH   8
#define DK   64
#define BSROWS (BB*SS)   // 8192
#define BH   (BB*NH)     // 32
#define NCT  (SS/64)     // 32 col tiles in scores

// projection outputs
__device__ __nv_bfloat16 g_qh[BH * SS * DK];
__device__ __nv_bfloat16 g_ql[BH * SS * DK];
__device__ __nv_bfloat16 g_kh[BH * SS * DK];
__device__ __nv_bfloat16 g_kl[BH * SS * DK];
__device__ __nv_bfloat16 g_vh[BH * SS * DK];       // plain bf16 (precision budget)
// pre-split / pre-converted inputs
__device__ __nv_bfloat16 g_inqh[BSROWS * EMB], g_inql[BSROWS * EMB];
__device__ __nv_bfloat16 g_inkh[BSROWS * EMB], g_inkl[BSROWS * EMB];
__device__ __nv_bfloat16 g_invh[BSROWS * EMB];
// weights
__device__ __nv_bfloat16 g_wqh[EMB * EMB], g_wql[EMB * EMB];
__device__ __nv_bfloat16 g_wkh[EMB * EMB], g_wkl[EMB * EMB];
__device__ __nv_bfloat16 g_wvh[EMB * EMB];
__device__ __nv_bfloat16 g_woh[EMB * EMB];
// context (plain bf16) + pre-LN sum
__device__ __nv_bfloat16 g_ctxh[BSROWS * EMB];
__device__ float g_x[BSROWS * EMB];
// softmax stats
__device__ float g_smax[(size_t)BH * SS * NCT];
__device__ float g_ssum[(size_t)BH * SS * NCT];
__device__ float g_rowm[(size_t)BH * SS];
__device__ float g_rinv[(size_t)BH * SS];

// ---------------------------------------------------------------------------
// helpers
// ---------------------------------------------------------------------------
__device__ __forceinline__ unsigned sptr(const void* p) {
    return (unsigned)__cvta_generic_to_shared(p);
}
__device__ __forceinline__ void ldsm4(unsigned* r, unsigned a) {
    asm volatile("ldmatrix.sync.aligned.m8n8.x4.shared.b16 {%0,%1,%2,%3}, [%4];"
                 : "=r"(r[0]), "=r"(r[1]), "=r"(r[2]), "=r"(r[3]) : "r"(a));
}
__device__ __forceinline__ void ldsm4t(unsigned* r, unsigned a) {
    asm volatile("ldmatrix.sync.aligned.m8n8.x4.trans.shared.b16 {%0,%1,%2,%3}, [%4];"
                 : "=r"(r[0]), "=r"(r[1]), "=r"(r[2]), "=r"(r[3]) : "r"(a));
}
__device__ __forceinline__ void mma_bf16(float* c, const unsigned* a, const unsigned* b) {
    asm volatile(
        "mma.sync.aligned.m16n8k16.row.col.f32.bf16.bf16.f32 "
        "{%0,%1,%2,%3},{%4,%5,%6,%7},{%8,%9},{%0,%1,%2,%3};"
        : "+f"(c[0]), "+f"(c[1]), "+f"(c[2]), "+f"(c[3])
        : "r"(a[0]), "r"(a[1]), "r"(a[2]), "r"(a[3]), "r"(b[0]), "r"(b[1]));
}
__device__ __forceinline__ void split_pair(float x, float y,
                                           __nv_bfloat162& h2, __nv_bfloat162& l2) {
    __nv_bfloat16 hx = __float2bfloat16_rn(x);
    __nv_bfloat16 hy = __float2bfloat16_rn(y);
    __nv_bfloat16 lx = __float2bfloat16_rn(x - __bfloat162float(hx));
    __nv_bfloat16 ly = __float2bfloat16_rn(y - __bfloat162float(hy));
    h2 = __halves2bfloat162(hx, hy);
    l2 = __halves2bfloat162(lx, ly);
}
__device__ __forceinline__ void cp16(unsigned dst, const void* src) {
    asm volatile("cp.async.cg.shared.global [%0], [%1], 16;" :: "r"(dst), "l"(src));
}
__device__ __forceinline__ void cp_commit() {
    asm volatile("cp.async.commit_group;");
}
__device__ __forceinline__ void cp_wait0() {
    asm volatile("cp.async.wait_group 0;");
}
__device__ __forceinline__ void cp_wait1() {
    asm volatile("cp.async.wait_group 1;");
}

// ---------------------------------------------------------------------------
// Batched conversions: Q,K -> hi/lo, V -> hi; Wq,Wk -> hi/lo, Wv,Wo -> hi.
// ---------------------------------------------------------------------------
__global__ __launch_bounds__(256) void split_inputs(
    const float* __restrict__ Q, const float* __restrict__ K,
    const float* __restrict__ V, int n4)
{
    int i = blockIdx.x * blockDim.x + threadIdx.x;
    if (i >= n4 * 3) return;
    int which = i / n4, j = i - which * n4;
    const float* in = which == 0 ? Q : which == 1 ? K : V;
    float4 v = ((const float4*)in)[j];
    __nv_bfloat162 h2, l2, h3, l3;
    split_pair(v.x, v.y, h2, l2);
    split_pair(v.z, v.w, h3, l3);
    __nv_bfloat16* hi = which == 0 ? g_inqh : which == 1 ? g_inkh : g_invh;
    ((__nv_bfloat162*)hi)[j * 2]     = h2;
    ((__nv_bfloat162*)hi)[j * 2 + 1] = h3;
    if (which < 2) {
        __nv_bfloat16* lo = which == 0 ? g_inql : g_inkl;
        ((__nv_bfloat162*)lo)[j * 2]     = l2;
        ((__nv_bfloat162*)lo)[j * 2 + 1] = l3;
    }
}

__global__ __launch_bounds__(256) void split_weights(
    const float* __restrict__ Wq, const float* __restrict__ Wk,
    const float* __restrict__ Wv, const float* __restrict__ Wo, int n4)
{
    int i = blockIdx.x * blockDim.x + threadIdx.x;
    if (i >= n4 * 4) return;
    int which = i / n4, j = i - which * n4;
    const float* in = which == 0 ? Wq : which == 1 ? Wk : which == 2 ? Wv : Wo;
    float4 v = ((const float4*)in)[j];
    __nv_bfloat162 h2, l2, h3, l3;
    split_pair(v.x, v.y, h2, l2);
    split_pair(v.z, v.w, h3, l3);
    __nv_bfloat16* hi = which == 0 ? g_wqh : which == 1 ? g_wkh
                      : which == 2 ? g_wvh : g_woh;
    ((__nv_bfloat162*)hi)[j * 2]     = h2;
    ((__nv_bfloat162*)hi)[j * 2 + 1] = h3;
    if (which < 2) {
        __nv_bfloat16* lo = which == 0 ? g_wql : g_wkl;
        ((__nv_bfloat162*)lo)[j * 2]     = l2;
        ((__nv_bfloat162*)lo)[j * 2 + 1] = l3;
    }
}

// ---------------------------------------------------------------------------
// Scores: per (b,h) 128x64 tile of q @ k^T * 0.125, masked, fp32 to attn.
// Split (3-product) MMA; coalesced smem-restaged epilogue + row stats.
// ---------------------------------------------------------------------------
#define SC_QH 0
#define SC_QL 18432
#define SC_KH 36864
#define SC_KL 46080
#define SC_SMEM 55296

__global__ __launch_bounds__(256, 3) void mma_scores(
    const unsigned char* __restrict__ mask, float* __restrict__ attn)
{
    extern __shared__ __align__(16) char smem_raw[];
    __nv_bfloat16 (*Qh)[72] = (__nv_bfloat16(*)[72])(smem_raw + SC_QH);
    __nv_bfloat16 (*Ql)[72] = (__nv_bfloat16(*)[72])(smem_raw + SC_QL);
    __nv_bfloat16 (*Kh)[72] = (__nv_bfloat16(*)[72])(smem_raw + SC_KH);
    __nv_bfloat16 (*Kl)[72] = (__nv_bfloat16(*)[72])(smem_raw + SC_KL);

    const int t = threadIdx.x, lane = t & 31, w = t >> 5;
    const int wm = w & 3, wn = w >> 2;
    const int bh = blockIdx.z, b = bh >> 3;
    const int r0 = blockIdx.y * 128, c0 = blockIdx.x * 64;
    const size_t base = (size_t)bh * SS * DK;

    #pragma unroll
    for (int i = 0; i < 12; i++) {
        int ch = t + i * 256;
        if (ch < 1024) {
            int r = ch >> 3, c8 = (ch & 7) * 8;
            cp16(sptr(&Qh[r][c8]), g_qh + base + (size_t)(r0 + r) * 64 + c8);
        } else if (ch < 2048) {
            int idx = ch - 1024, r = idx >> 3, c8 = (idx & 7) * 8;
            cp16(sptr(&Ql[r][c8]), g_ql + base + (size_t)(r0 + r) * 64 + c8);
        } else if (ch < 2560) {
            int idx = ch - 2048, r = idx >> 3, c8 = (idx & 7) * 8;
            cp16(sptr(&Kh[r][c8]), g_kh + base + (size_t)(c0 + r) * 64 + c8);
        } else {
            int idx = ch - 2560, r = idx >> 3, c8 = (idx & 7) * 8;
            cp16(sptr(&Kl[r][c8]), g_kl + base + (size_t)(c0 + r) * 64 + c8);
        }
    }
    cp_commit();
    cp_wait0();
    __syncthreads();

    float acc[2][4][4] = {};
    #pragma unroll
    for (int k2 = 0; k2 < 64; k2 += 16) {
        unsigned ah[2][4], al[2][4];
        #pragma unroll
        for (int mi = 0; mi < 2; mi++) {
            int r = wm * 32 + mi * 16 + (lane & 15);
            int c = k2 + ((lane >> 4) << 3);
            ldsm4(ah[mi], sptr(&Qh[r][c]));
            ldsm4(al[mi], sptr(&Ql[r][c]));
        }
        #pragma unroll
        for (int g = 0; g < 2; g++) {
            int nr = wn * 32 + g * 16 + (lane & 7) + ((lane >> 4) << 3);
            int kc = k2 + (((lane >> 3) & 1) << 3);
            unsigned bh_[4], bl_[4];
            ldsm4(bh_, sptr(&Kh[nr][kc]));
            ldsm4(bl_, sptr(&Kl[nr][kc]));
            #pragma unroll
            for (int mi = 0; mi < 2; mi++) {
                mma_bf16(acc[mi][2*g],   ah[mi], &bh_[0]);
                mma_bf16(acc[mi][2*g+1], ah[mi], &bh_[2]);
                mma_bf16(acc[mi][2*g],   ah[mi], &bl_[0]);
                mma_bf16(acc[mi][2*g+1], ah[mi], &bl_[2]);
                mma_bf16(acc[mi][2*g],   al[mi], &bh_[0]);
                mma_bf16(acc[mi][2*g+1], al[mi], &bh_[2]);
            }
        }
    }

    // restage through smem: [128][68] fp32, halves at col offsets 0/34
    __syncthreads();
    float* stg = (float*)smem_raw;
    #pragma unroll
    for (int mi = 0; mi < 2; mi++) {
        #pragma unroll
        for (int nf = 0; nf < 4; nf++) {
            float* c = acc[mi][nf];
            int r = wm * 32 + mi * 16 + (lane >> 2);
            int cc = wn * 34 + nf * 8 + (lane & 3) * 2;
            *(float2*)&stg[r * 68 + cc]       = make_float2(c[0], c[1]);
            *(float2*)&stg[(r + 8) * 68 + cc] = make_float2(c[2], c[3]);
        }
    }
    __syncthreads();

    {
        const int colg = lane * 2;
        const int colp = colg + (lane >= 16 ? 2 : 0);
        #pragma unroll 4
        for (int r = 0; r < 16; r++) {
            int row = w * 16 + r;
            float2 v = *(float2*)&stg[row * 68 + colp];
            size_t gr = (size_t)(r0 + row);
            const unsigned char* mp = mask + ((size_t)b * SS + gr) * SS + c0 + colg;
            v.x = mp[0] ? -1e9f : v.x * 0.125f;
            v.y = mp[1] ? -1e9f : v.y * 0.125f;
            *(float2*)(attn + ((size_t)bh * SS + gr) * SS + c0 + colg) = v;
            float mx = fmaxf(v.x, v.y);
            #pragma unroll
            for (int o = 16; o; o >>= 1) mx = fmaxf(mx, __shfl_xor_sync(0xffffffffu, mx, o));
            float s = __expf(v.x - mx) + __expf(v.y - mx);
            #pragma unroll
            for (int o = 16; o; o >>= 1) s += __shfl_xor_sync(0xffffffffu, s, o);
            if (lane == 0) {
                size_t idx = ((size_t)bh * SS + gr) * NCT + blockIdx.x;
                g_smax[idx] = mx;
                g_ssum[idx] = s;
            }
        }
    }
}

// ---------------------------------------------------------------------------
// Combine tile stats into per-row max and 1/sum. One warp per row.
// ---------------------------------------------------------------------------
__global__ __launch_bounds__(256) void softmax_stats(
    float* __restrict__ rowm, float* __restrict__ rinv)
{
    const int w = threadIdx.x >> 5, lane = threadIdx.x & 31;
    const size_t rg = (size_t)blockIdx.x * 8 + w;
    float m_l = g_smax[rg * NCT + lane];
    float s_l = g_ssum[rg * NCT + lane];
    float m = m_l;
    #pragma unroll
    for (int o = 16; o; o >>= 1) m = fmaxf(m, __shfl_xor_sync(0xffffffffu, m, o));
    float c = __expf(m_l - m) * s_l;
    #pragma unroll
    for (int o = 16; o; o >>= 1) c += __shfl_xor_sync(0xffffffffu, c, o);
    if (lane == 0) { rowm[rg] = m; rinv[rg] = 1.0f / c; }
}

// ---------------------------------------------------------------------------
// GEMM: C = A[M,512] @ W[512,512] + bias (+resid). Block 128x64, 256 thr,
// double-buffered cp.async. SPLIT=1: 3-product hi/lo; SPLIT=0: plain bf16.
// ---------------------------------------------------------------------------
template<int SPLIT>
struct GOff {
    static const unsigned AH = 0;
    static const unsigned AL = 20480;
    static const unsigned WH = SPLIT ? 40960u : 20480u;
    static const unsigned WL = 50176;
    static const unsigned ABUF = 10240;
    static const unsigned WBUF = 4608;
    static const unsigned SMEM = SPLIT ? 59392u : 29696u;
};

template<int SPLIT>
__device__ __forceinline__ void gload(
    unsigned sb, int buf,
    const __nv_bfloat16* __restrict__ Ah, const __nv_bfloat16* __restrict__ Al,
    const __nv_bfloat16* __restrict__ Wh, const __nv_bfloat16* __restrict__ Wl,
    int row0, int col0, int kk, int t)
{
    #pragma unroll
    for (int i = 0; i < 2; i++) {
        int ch = t + i * 256;
        int r = ch >> 2, c = (ch & 3) * 8;
        unsigned off = buf * GOff<SPLIT>::ABUF + r * 80 + c * 2;
        cp16(sb + GOff<SPLIT>::AH + off, Ah + (size_t)(row0 + r) * 512 + kk + c);
        if (SPLIT)
            cp16(sb + GOff<SPLIT>::AL + off, Al + (size_t)(row0 + r) * 512 + kk + c);
    }
    {
        int r = t >> 3, c = (t & 7) * 8;
        unsigned off = buf * GOff<SPLIT>::WBUF + r * 144 + c * 2;
        cp16(sb + GOff<SPLIT>::WH + off, Wh + (size_t)(kk + r) * 512 + col0 + c);
        if (SPLIT)
            cp16(sb + GOff<SPLIT>::WL + off, Wl + (size_t)(kk + r) * 512 + col0 + c);
    }
}

template<int OUTPROJ, int SPLIT, int OUTLO>
__global__ __launch_bounds__(256, 3) void mma_gemm512(
    const __nv_bfloat16* __restrict__ Ah, const __nv_bfloat16* __restrict__ Al,
    const __nv_bfloat16* __restrict__ Wh, const __nv_bfloat16* __restrict__ Wl,
    const float* __restrict__ bias, const float* __restrict__ resid,
    __nv_bfloat16* __restrict__ Oh, __nv_bfloat16* __restrict__ Ol,
    float* __restrict__ Of)
{
    extern __shared__ __align__(16) char smem_raw[];
    const unsigned sb = sptr(smem_raw);
    const int t = threadIdx.x, lane = t & 31, w = t >> 5;
    const int wm = w & 3, wn = w >> 2;
    const int row0 = blockIdx.y * 128, col0 = blockIdx.x * 64;

    float acc[2][4][4] = {};

    gload<SPLIT>(sb, 0, Ah, Al, Wh, Wl, row0, col0, 0, t);
    cp_commit();

    for (int it = 0; it < 16; it++) {
        if (it < 15)
            gload<SPLIT>(sb, (it + 1) & 1, Ah, Al, Wh, Wl, row0, col0, (it + 1) * 32, t);
        cp_commit();
        cp_wait1();
        __syncthreads();

        const unsigned abh = sb + GOff<SPLIT>::AH + (it & 1) * GOff<SPLIT>::ABUF;
        const unsigned abl = sb + GOff<SPLIT>::AL + (it & 1) * GOff<SPLIT>::ABUF;
        const unsigned wbh = sb + GOff<SPLIT>::WH + (it & 1) * GOff<SPLIT>::WBUF;
        const unsigned wbl = sb + GOff<SPLIT>::WL + (it & 1) * GOff<SPLIT>::WBUF;

        #pragma unroll
        for (int k2 = 0; k2 < 32; k2 += 16) {
            unsigned ah[2][4], al[2][4];
            #pragma unroll
            for (int mi = 0; mi < 2; mi++) {
                int r = wm * 32 + mi * 16 + (lane & 15);
                int c = k2 + ((lane >> 4) << 3);
                ldsm4(ah[mi], abh + r * 80 + c * 2);
                if (SPLIT) ldsm4(al[mi], abl + r * 80 + c * 2);
            }
            #pragma unroll
            for (int g = 0; g < 2; g++) {
                int kr = k2 + (lane & 7) + (((lane >> 3) & 1) << 3);
                int nc = wn * 32 + g * 16 + ((lane >> 4) << 3);
                unsigned bh_[4], bl_[4];
                ldsm4t(bh_, wbh + kr * 144 + nc * 2);
                if (SPLIT) ldsm4t(bl_, wbl + kr * 144 + nc * 2);
                #pragma unroll
                for (int mi = 0; mi < 2; mi++) {
                    mma_bf16(acc[mi][2*g],   ah[mi], &bh_[0]);
                    mma_bf16(acc[mi][2*g+1], ah[mi], &bh_[2]);
                    if (SPLIT) {
                        mma_bf16(acc[mi][2*g],   ah[mi], &bl_[0]);
                        mma_bf16(acc[mi][2*g+1], ah[mi], &bl_[2]);
                        mma_bf16(acc[mi][2*g],   al[mi], &bh_[0]);
                        mma_bf16(acc[mi][2*g+1], al[mi], &bh_[2]);
                    }
                }
            }
        }
        __syncthreads();
    }

    #pragma unroll
    for (int mi = 0; mi < 2; mi++) {
        #pragma unroll
        for (int nf = 0; nf < 4; nf++) {
            float* c = acc[mi][nf];
            int m = row0 + wm * 32 + mi * 16 + (lane >> 2);
            int n = col0 + wn * 32 + nf * 8 + ((lane & 3) << 1);
            float b0 = bias[n], b1 = bias[n + 1];
            if (OUTPROJ) {
                float2 r = *(const float2*)(resid + (size_t)m * 512 + n);
                *(float2*)(Of + (size_t)m * 512 + n) =
                    make_float2(c[0] + b0 + r.x, c[1] + b1 + r.y);
                r = *(const float2*)(resid + (size_t)(m + 8) * 512 + n);
                *(float2*)(Of + (size_t)(m + 8) * 512 + n) =
                    make_float2(c[2] + b0 + r.x, c[3] + b1 + r.y);
            } else {
                int h = n >> 6, d = n & 63;
                int b = m >> 11, s = m & 2047;
                size_t base = ((size_t)(b * NH + h) * SS + s) * DK + d;
                if (OUTLO) {
                    __nv_bfloat162 h2, l2;
                    split_pair(c[0] + b0, c[1] + b1, h2, l2);
                    *(__nv_bfloat162*)&Oh[base] = h2;
                    *(__nv_bfloat162*)&Ol[base] = l2;
                    split_pair(c[2] + b0, c[3] + b1, h2, l2);
                    *(__nv_bfloat162*)&Oh[base + 8 * (size_t)DK] = h2;
                    *(__nv_bfloat162*)&Ol[base + 8 * (size_t)DK] = l2;
                } else {
                    *(__nv_bfloat162*)&Oh[base] =
                        __float22bfloat162_rn(make_float2(c[0] + b0, c[1] + b1));
                    *(__nv_bfloat162*)&Oh[base + 8 * (size_t)DK] =
                        __float22bfloat162_rn(make_float2(c[2] + b0, c[3] + b1));
                }
            }
        }
    }
}

// ---------------------------------------------------------------------------
// Context + softmax normalize, pure bf16 P and V.
// Pipelined: raw P scores + V staged via double-buffered cp.async so global
// loads overlap exp/MMA of the previous chunk. (256,2) ONLY — the 80-reg
// (256,3) clamp spills the fused exp loop (rounds 6, 11). Do not retry.
// ---------------------------------------------------------------------------
#define CT_PRAW 0
#define CT_PBUF 34816                       // 128 rows * 68 floats * 4B
#define CT_PH   (2 * CT_PBUF)               // 69632; 128x72 bf16 = 18432
#define CT_VH   (CT_PH + 18432)             // 88064; 2 x 64x72 bf16
#define CT_VBUF 9216
#define CT_SMEM (CT_VH + 2 * CT_VBUF)       // 106496

__global__ __launch_bounds__(256, 2) void mma_context(
    float* __restrict__ attn, const float* __restrict__ rowm,
    const float* __restrict__ rinv, __nv_bfloat16* __restrict__ ctxh)
{
    extern __shared__ __align__(16) char smem_raw[];
    const unsigned sb = sptr(smem_raw);
    __nv_bfloat16 (*Ph)[72] = (__nv_bfloat16(*)[72])(smem_raw + CT_PH);

    const int t = threadIdx.x, lane = t & 31, w = t >> 5;
    const int wm = w & 3, wn = w >> 2;
    const int bh = blockIdx.y, r0 = blockIdx.x * 128;
    const size_t vbase = (size_t)bh * SS * DK;
    const float* arow_base = attn + (size_t)bh * SS * SS + (size_t)r0 * SS;

    const int pr = t >> 1, pc = (t & 1) * 32;
    const float rm = __ldg(rowm + (size_t)bh * SS + r0 + pr);
    const float ri = __ldg(rinv + (size_t)bh * SS + r0 + pr);
    float* prow = attn + (size_t)bh * SS * SS + (size_t)(r0 + pr) * SS + pc;

    float acc[2][4][4] = {};

    // chunk loader: raw P (128x64 fp32, padded 68) + V (64x64 bf16)
    #define CT_LOAD(kk, buf) do {                                              \
        unsigned pb = sb + CT_PRAW + (buf) * CT_PBUF;                          \
        _Pragma("unroll")                                                      \
        for (int i = 0; i < 8; i++) {                                          \
            int ch = t + i * 256;                                              \
            int row = ch >> 4, seg = ch & 15;                                  \
            cp16(pb + row * 272 + seg * 16,                                    \
                 arow_base + (size_t)row * SS + (kk) + seg * 4);               \
        }                                                                      \
        unsigned vb = sb + CT_VH + (buf) * CT_VBUF;                            \
        _Pragma("unroll")                                                      \
        for (int i = 0; i < 2; i++) {                                          \
            int idx = t + i * 256;                                             \
            int vr = idx >> 3, vc = (idx & 7) * 8;                             \
            cp16(vb + vr * 144 + vc * 2,                                       \
                 g_vh + vbase + (size_t)((kk) + vr) * 64 + vc);                \
        }                                                                      \
    } while (0)

    CT_LOAD(0, 0);
    cp_commit();

    for (int it = 0; it < 32; it++) {
        const int buf = it & 1;
        if (it < 31) CT_LOAD((it + 1) * 64, buf ^ 1);
        cp_commit();
        cp_wait1();            // current chunk's group complete
        __syncthreads();

        {   // process: exp from smem raw, write probs to gmem, pack Ph
            const float* praw = (const float*)(smem_raw + CT_PRAW + buf * CT_PBUF);
            float* pout = prow + it * 64;
            #pragma unroll
            for (int i = 0; i < 32; i += 4) {
                float4 v = *(const float4*)&praw[pr * 68 + pc + i];
                v.x = __expf(v.x - rm) * ri;
                v.y = __expf(v.y - rm) * ri;
                v.z = __expf(v.z - rm) * ri;
                v.w = __expf(v.w - rm) * ri;
                *(float4*)(pout + i) = v;            // final attn probabilities
                *(__nv_bfloat162*)&Ph[pr][pc + i] =
                    __float22bfloat162_rn(make_float2(v.x, v.y));
                *(__nv_bfloat162*)&Ph[pr][pc + i + 2] =
                    __float22bfloat162_rn(make_float2(v.z, v.w));
            }
        }
        __syncthreads();

        const unsigned vb = sb + CT_VH + buf * CT_VBUF;
        #pragma unroll
        for (int k2 = 0; k2 < 64; k2 += 16) {
            unsigned ah[2][4];
            #pragma unroll
            for (int mi = 0; mi < 2; mi++) {
                int r = wm * 32 + mi * 16 + (lane & 15);
                int c = k2 + ((lane >> 4) << 3);
                ldsm4(ah[mi], sptr(&Ph[r][c]));
            }
            #pragma unroll
            for (int g = 0; g < 2; g++) {
                int kr = k2 + (lane & 7) + (((lane >> 3) & 1) << 3);
                int nc = wn * 32 + g * 16 + ((lane >> 4) << 3);
                unsigned bh_[4];
                ldsm4t(bh_, vb + kr * 144 + nc * 2);
                #pragma unroll
                for (int mi = 0; mi < 2; mi++) {
                    mma_bf16(acc[mi][2*g],   ah[mi], &bh_[0]);
                    mma_bf16(acc[mi][2*g+1], ah[mi], &bh_[2]);
                }
            }
        }
        __syncthreads();
    }
    #undef CT_LOAD

    const int b = bh >> 3, h = bh & 7;
    #pragma unroll
    for (int mi = 0; mi < 2; mi++) {
        #pragma unroll
        for (int nf = 0; nf < 4; nf++) {
            float* c = acc[mi][nf];
            int m = r0 + wm * 32 + mi * 16 + (lane >> 2);
            int n = wn * 32 + nf * 8 + ((lane & 3) << 1);
            size_t idx = ((size_t)(b * SS + m)) * EMB + h * DK + n;
            *(__nv_bfloat162*)&ctxh[idx] =
                __float22bfloat162_rn(make_float2(c[0], c[1]));
            *(__nv_bfloat162*)&ctxh[idx + 8 * (size_t)EMB] =
                __float22bfloat162_rn(make_float2(c[2], c[3]));
        }
    }
}

// ---------------------------------------------------------------------------
// LayerNorm over 512.
// ---------------------------------------------------------------------------
__global__ __launch_bounds__(128) void ln_kernel(
    const float* __restrict__ gamma, const float* __restrict__ beta,
    float* __restrict__ out)
{
    const size_t row = blockIdx.x;
    const int t = threadIdx.x;
    const float* x = g_x + row * EMB;
    __shared__ float rs[4], rq[4];

    float4 v = ((const float4*)x)[t];
    float s  = v.x + v.y + v.z + v.w;
    float sq = v.x*v.x + v.y*v.y + v.z*v.z + v.w*v.w;
    #pragma unroll
    for (int o = 16; o; o >>= 1) {
        s  += __shfl_xor_sync(0xffffffffu, s,  o);
        sq += __shfl_xor_sync(0xffffffffu, sq, o);
    }
    if ((t & 31) == 0) { rs[t >> 5] = s; rq[t >> 5] = sq; }
    __syncthreads();
    s  = rs[0] + rs[1] + rs[2] + rs[3];
    sq = rq[0] + rq[1] + rq[2] + rq[3];

    float mu  = s * (1.0f / 512.0f);
    float var = sq * (1.0f / 512.0f) - mu * mu;
    float inv = rsqrtf(var + 1e-5f);

    float4 g = ((const float4*)gamma)[t];
    float4 bb = ((const float4*)beta)[t];
    float4 o;
    o.x = (v.x - mu) * inv * g.x + bb.x;
    o.y = (v.y - mu) * inv * g.y + bb.y;
    o.z = (v.z - mu) * inv * g.z + bb.z;
    o.w = (v.w - mu) * inv * g.w + bb.w;
    ((float4*)(out + row * EMB))[t] = o;
}

// ---------------------------------------------------------------------------
extern "C" void kernel_launch(void* const* d_in, const int* in_sizes, int n_in,
                              void* d_out, int out_size)
{
    const float* Q  = (const float*)d_in[0];
    const float* K  = (const float*)d_in[1];
    const float* V  = (const float*)d_in[2];
    const unsigned char* mask = (const unsigned char*)d_in[3];
    const float* Wq = (const float*)d_in[4];
    const float* bq = (const float*)d_in[5];
    const float* Wk = (const float*)d_in[6];
    const float* bk = (const float*)d_in[7];
    const float* Wv = (const float*)d_in[8];
    const float* bv = (const float*)d_in[9];
    const float* Wo = (const float*)d_in[10];
    const float* bo = (const float*)d_in[11];
    const float* gamma = (const float*)d_in[12];
    const float* beta  = (const float*)d_in[13];

    float* out  = (float*)d_out;
    float* attn = out + (size_t)BSROWS * EMB;

    __nv_bfloat16 *qh, *ql, *kh, *kl, *vh;
    __nv_bfloat16 *inqh, *inql, *inkh, *inkl, *invh;
    __nv_bfloat16 *wqh, *wql, *wkh, *wkl, *wvh, *woh;
    __nv_bfloat16 *ctxh;
    float *xp, *rowmp, *rinvp;
    cudaGetSymbolAddress((void**)&qh, g_qh);
    cudaGetSymbolAddress((void**)&ql, g_ql);
    cudaGetSymbolAddress((void**)&kh, g_kh);
    cudaGetSymbolAddress((void**)&kl, g_kl);
    cudaGetSymbolAddress((void**)&vh, g_vh);
    cudaGetSymbolAddress((void**)&inqh, g_inqh);
    cudaGetSymbolAddress((void**)&inql, g_inql);
    cudaGetSymbolAddress((void**)&inkh, g_inkh);
    cudaGetSymbolAddress((void**)&inkl, g_inkl);
    cudaGetSymbolAddress((void**)&invh, g_invh);
    cudaGetSymbolAddress((void**)&wqh, g_wqh);
    cudaGetSymbolAddress((void**)&wql, g_wql);
    cudaGetSymbolAddress((void**)&wkh, g_wkh);
    cudaGetSymbolAddress((void**)&wkl, g_wkl);
    cudaGetSymbolAddress((void**)&wvh, g_wvh);
    cudaGetSymbolAddress((void**)&woh, g_woh);
    cudaGetSymbolAddress((void**)&ctxh, g_ctxh);
    cudaGetSymbolAddress((void**)&xp,   g_x);
    cudaGetSymbolAddress((void**)&rowmp, g_rowm);
    cudaGetSymbolAddress((void**)&rinvp, g_rinv);

    cudaFuncSetAttribute(mma_scores, cudaFuncAttributeMaxDynamicSharedMemorySize,
                         SC_SMEM);
    cudaFuncSetAttribute(mma_gemm512<0,1,1>, cudaFuncAttributeMaxDynamicSharedMemorySize,
                         GOff<1>::SMEM);
    cudaFuncSetAttribute(mma_gemm512<0,0,0>, cudaFuncAttributeMaxDynamicSharedMemorySize,
                         GOff<0>::SMEM);
    cudaFuncSetAttribute(mma_gemm512<1,0,0>, cudaFuncAttributeMaxDynamicSharedMemorySize,
                         GOff<0>::SMEM);
    cudaFuncSetAttribute(mma_context, cudaFuncAttributeMaxDynamicSharedMemorySize,
                         CT_SMEM);

    // batched conversions
    const int n4_in = BSROWS * EMB / 4;       // 1,048,576
    const int n4_w  = EMB * EMB / 4;          // 65,536
    split_inputs<<<(n4_in * 3 + 255) / 256, 256>>>(Q, K, V, n4_in);
    split_weights<<<(n4_w * 4 + 255) / 256, 256>>>(Wq, Wk, Wv, Wo, n4_w);

    dim3 gemm_grid(EMB / 64, BSROWS / 128);        // 8 x 64
    mma_gemm512<0,1,1><<<gemm_grid, 256, GOff<1>::SMEM>>>(
        inqh, inql, wqh, wql, bq, nullptr, qh, ql, nullptr);
    mma_gemm512<0,1,1><<<gemm_grid, 256, GOff<1>::SMEM>>>(
        inkh, inkl, wkh, wkl, bk, nullptr, kh, kl, nullptr);
    mma_gemm512<0,0,0><<<gemm_grid, 256, GOff<0>::SMEM>>>(
        invh, nullptr, wvh, nullptr, bv, nullptr, vh, nullptr, nullptr);

    dim3 sc_grid(SS / 64, SS / 128, BH);           // 32 x 16 x 32
    mma_scores<<<sc_grid, 256, SC_SMEM>>>(mask, attn);

    softmax_stats<<<(BH * SS) / 8, 256>>>(rowmp, rinvp);

    dim3 ctx_grid(SS / 128, BH);                   // 16 x 32
    mma_context<<<ctx_grid, 256, CT_SMEM>>>(attn, rowmp, rinvp, ctxh);

    mma_gemm512<1,0,0><<<gemm_grid, 256, GOff<0>::SMEM>>>(
        ctxh, nullptr, woh, nullptr, bo, Q, nullptr, nullptr, xp);

    ln_kernel<<<BSROWS, 128>>>(gamma, beta, out);
}

// round 14
// speedup vs baseline: 1.7463x; 1.2526x over previous
#include <cuda_runtime.h>
#include <cuda_bf16.h>
#include <math.h>

#define BB   4
#define SS   2048
#define EMB  512
#define NH   8
#define DK   64
#define BSROWS (BB*SS)   // 8192
#define BH   (BB*NH)     // 32
#define NCT  (SS/64)     // 32 col tiles in scores

// projection outputs
__device__ __nv_bfloat16 g_qh[BH * SS * DK];
__device__ __nv_bfloat16 g_ql[BH * SS * DK];
__device__ __nv_bfloat16 g_kh[BH * SS * DK];
__device__ __nv_bfloat16 g_kl[BH * SS * DK];
__device__ __nv_bfloat16 g_vh[BH * SS * DK];       // plain bf16 (precision budget)
// pre-split / pre-converted inputs
__device__ __nv_bfloat16 g_inqh[BSROWS * EMB], g_inql[BSROWS * EMB];
__device__ __nv_bfloat16 g_inkh[BSROWS * EMB], g_inkl[BSROWS * EMB];
__device__ __nv_bfloat16 g_invh[BSROWS * EMB];
// weights
__device__ __nv_bfloat16 g_wqh[EMB * EMB], g_wql[EMB * EMB];
__device__ __nv_bfloat16 g_wkh[EMB * EMB], g_wkl[EMB * EMB];
__device__ __nv_bfloat16 g_wvh[EMB * EMB];
__device__ __nv_bfloat16 g_woh[EMB * EMB];
// context (plain bf16) + pre-LN sum
__device__ __nv_bfloat16 g_ctxh[BSROWS * EMB];
__device__ float g_x[BSROWS * EMB];
// softmax stats
__device__ float g_smax[(size_t)BH * SS * NCT];
__device__ float g_ssum[(size_t)BH * SS * NCT];
__device__ float g_rowm[(size_t)BH * SS];
__device__ float g_rinv[(size_t)BH * SS];

// ---------------------------------------------------------------------------
// helpers
// ---------------------------------------------------------------------------
__device__ __forceinline__ unsigned sptr(const void* p) {
    return (unsigned)__cvta_generic_to_shared(p);
}
__device__ __forceinline__ void ldsm4(unsigned* r, unsigned a) {
    asm volatile("ldmatrix.sync.aligned.m8n8.x4.shared.b16 {%0,%1,%2,%3}, [%4];"
                 : "=r"(r[0]), "=r"(r[1]), "=r"(r[2]), "=r"(r[3]) : "r"(a));
}
__device__ __forceinline__ void ldsm4t(unsigned* r, unsigned a) {
    asm volatile("ldmatrix.sync.aligned.m8n8.x4.trans.shared.b16 {%0,%1,%2,%3}, [%4];"
                 : "=r"(r[0]), "=r"(r[1]), "=r"(r[2]), "=r"(r[3]) : "r"(a));
}
__device__ __forceinline__ void mma_bf16(float* c, const unsigned* a, const unsigned* b) {
    asm volatile(
        "mma.sync.aligned.m16n8k16.row.col.f32.bf16.bf16.f32 "
        "{%0,%1,%2,%3},{%4,%5,%6,%7},{%8,%9},{%0,%1,%2,%3};"
        : "+f"(c[0]), "+f"(c[1]), "+f"(c[2]), "+f"(c[3])
        : "r"(a[0]), "r"(a[1]), "r"(a[2]), "r"(a[3]), "r"(b[0]), "r"(b[1]));
}
__device__ __forceinline__ void split_pair(float x, float y,
                                           __nv_bfloat162& h2, __nv_bfloat162& l2) {
    __nv_bfloat16 hx = __float2bfloat16_rn(x);
    __nv_bfloat16 hy = __float2bfloat16_rn(y);
    __nv_bfloat16 lx = __float2bfloat16_rn(x - __bfloat162float(hx));
    __nv_bfloat16 ly = __float2bfloat16_rn(y - __bfloat162float(hy));
    h2 = __halves2bfloat162(hx, hy);
    l2 = __halves2bfloat162(lx, ly);
}
__device__ __forceinline__ void cp16(unsigned dst, const void* src) {
    asm volatile("cp.async.cg.shared.global [%0], [%1], 16;" :: "r"(dst), "l"(src));
}
__device__ __forceinline__ void cp_commit() {
    asm volatile("cp.async.commit_group;");
}
__device__ __forceinline__ void cp_wait0() {
    asm volatile("cp.async.wait_group 0;");
}
__device__ __forceinline__ void cp_wait1() {
    asm volatile("cp.async.wait_group 1;");
}

// ---------------------------------------------------------------------------
// Merged conversions: inputs (Q,K hi/lo; V hi) then weights (Wq,Wk hi/lo;
// Wv,Wo hi) in a single launch.
// ---------------------------------------------------------------------------
__global__ __launch_bounds__(256) void convert_all(
    const float* __restrict__ Q, const float* __restrict__ K,
    const float* __restrict__ V,
    const float* __restrict__ Wq, const float* __restrict__ Wk,
    const float* __restrict__ Wv, const float* __restrict__ Wo,
    int n4_in, int nblk_in, int n4_w)
{
    if ((int)blockIdx.x < nblk_in) {
        int i = blockIdx.x * blockDim.x + threadIdx.x;
        if (i >= n4_in * 3) return;
        int which = i / n4_in, j = i - which * n4_in;
        const float* in = which == 0 ? Q : which == 1 ? K : V;
        float4 v = ((const float4*)in)[j];
        __nv_bfloat162 h2, l2, h3, l3;
        split_pair(v.x, v.y, h2, l2);
        split_pair(v.z, v.w, h3, l3);
        __nv_bfloat16* hi = which == 0 ? g_inqh : which == 1 ? g_inkh : g_invh;
        ((__nv_bfloat162*)hi)[j * 2]     = h2;
        ((__nv_bfloat162*)hi)[j * 2 + 1] = h3;
        if (which < 2) {
            __nv_bfloat16* lo = which == 0 ? g_inql : g_inkl;
            ((__nv_bfloat162*)lo)[j * 2]     = l2;
            ((__nv_bfloat162*)lo)[j * 2 + 1] = l3;
        }
    } else {
        int i = (blockIdx.x - nblk_in) * blockDim.x + threadIdx.x;
        if (i >= n4_w * 4) return;
        int which = i / n4_w, j = i - which * n4_w;
        const float* in = which == 0 ? Wq : which == 1 ? Wk : which == 2 ? Wv : Wo;
        float4 v = ((const float4*)in)[j];
        __nv_bfloat162 h2, l2, h3, l3;
        split_pair(v.x, v.y, h2, l2);
        split_pair(v.z, v.w, h3, l3);
        __nv_bfloat16* hi = which == 0 ? g_wqh : which == 1 ? g_wkh
                          : which == 2 ? g_wvh : g_woh;
        ((__nv_bfloat162*)hi)[j * 2]     = h2;
        ((__nv_bfloat162*)hi)[j * 2 + 1] = h3;
        if (which < 2) {
            __nv_bfloat16* lo = which == 0 ? g_wql : g_wkl;
            ((__nv_bfloat162*)lo)[j * 2]     = l2;
            ((__nv_bfloat162*)lo)[j * 2 + 1] = l3;
        }
    }
}

// ---------------------------------------------------------------------------
// Scores: per (b,h) 128x64 tile of q @ k^T * 0.125, masked, fp32 to attn.
// Split (3-product) MMA; coalesced smem-restaged epilogue + row stats.
// ---------------------------------------------------------------------------
#define SC_QH 0
#define SC_QL 18432
#define SC_KH 36864
#define SC_KL 46080
#define SC_SMEM 55296

__global__ __launch_bounds__(256, 3) void mma_scores(
    const unsigned char* __restrict__ mask, float* __restrict__ attn)
{
    extern __shared__ __align__(16) char smem_raw[];
    __nv_bfloat16 (*Qh)[72] = (__nv_bfloat16(*)[72])(smem_raw + SC_QH);
    __nv_bfloat16 (*Ql)[72] = (__nv_bfloat16(*)[72])(smem_raw + SC_QL);
    __nv_bfloat16 (*Kh)[72] = (__nv_bfloat16(*)[72])(smem_raw + SC_KH);
    __nv_bfloat16 (*Kl)[72] = (__nv_bfloat16(*)[72])(smem_raw + SC_KL);

    const int t = threadIdx.x, lane = t & 31, w = t >> 5;
    const int wm = w & 3, wn = w >> 2;
    const int bh = blockIdx.z, b = bh >> 3;
    const int r0 = blockIdx.y * 128, c0 = blockIdx.x * 64;
    const size_t base = (size_t)bh * SS * DK;

    #pragma unroll
    for (int i = 0; i < 12; i++) {
        int ch = t + i * 256;
        if (ch < 1024) {
            int r = ch >> 3, c8 = (ch & 7) * 8;
            cp16(sptr(&Qh[r][c8]), g_qh + base + (size_t)(r0 + r) * 64 + c8);
        } else if (ch < 2048) {
            int idx = ch - 1024, r = idx >> 3, c8 = (idx & 7) * 8;
            cp16(sptr(&Ql[r][c8]), g_ql + base + (size_t)(r0 + r) * 64 + c8);
        } else if (ch < 2560) {
            int idx = ch - 2048, r = idx >> 3, c8 = (idx & 7) * 8;
            cp16(sptr(&Kh[r][c8]), g_kh + base + (size_t)(c0 + r) * 64 + c8);
        } else {
            int idx = ch - 2560, r = idx >> 3, c8 = (idx & 7) * 8;
            cp16(sptr(&Kl[r][c8]), g_kl + base + (size_t)(c0 + r) * 64 + c8);
        }
    }
    cp_commit();
    cp_wait0();
    __syncthreads();

    float acc[2][4][4] = {};
    #pragma unroll
    for (int k2 = 0; k2 < 64; k2 += 16) {
        unsigned ah[2][4], al[2][4];
        #pragma unroll
        for (int mi = 0; mi < 2; mi++) {
            int r = wm * 32 + mi * 16 + (lane & 15);
            int c = k2 + ((lane >> 4) << 3);
            ldsm4(ah[mi], sptr(&Qh[r][c]));
            ldsm4(al[mi], sptr(&Ql[r][c]));
        }
        #pragma unroll
        for (int g = 0; g < 2; g++) {
            int nr = wn * 32 + g * 16 + (lane & 7) + ((lane >> 4) << 3);
            int kc = k2 + (((lane >> 3) & 1) << 3);
            unsigned bh_[4], bl_[4];
            ldsm4(bh_, sptr(&Kh[nr][kc]));
            ldsm4(bl_, sptr(&Kl[nr][kc]));
            #pragma unroll
            for (int mi = 0; mi < 2; mi++) {
                mma_bf16(acc[mi][2*g],   ah[mi], &bh_[0]);
                mma_bf16(acc[mi][2*g+1], ah[mi], &bh_[2]);
                mma_bf16(acc[mi][2*g],   ah[mi], &bl_[0]);
                mma_bf16(acc[mi][2*g+1], ah[mi], &bl_[2]);
                mma_bf16(acc[mi][2*g],   al[mi], &bh_[0]);
                mma_bf16(acc[mi][2*g+1], al[mi], &bh_[2]);
            }
        }
    }

    // restage through smem: [128][68] fp32, halves at col offsets 0/34
    __syncthreads();
    float* stg = (float*)smem_raw;
    #pragma unroll
    for (int mi = 0; mi < 2; mi++) {
        #pragma unroll
        for (int nf = 0; nf < 4; nf++) {
            float* c = acc[mi][nf];
            int r = wm * 32 + mi * 16 + (lane >> 2);
            int cc = wn * 34 + nf * 8 + (lane & 3) * 2;
            *(float2*)&stg[r * 68 + cc]       = make_float2(c[0], c[1]);
            *(float2*)&stg[(r + 8) * 68 + cc] = make_float2(c[2], c[3]);
        }
    }
    __syncthreads();

    {
        const int colg = lane * 2;
        const int colp = colg + (lane >= 16 ? 2 : 0);
        #pragma unroll 4
        for (int r = 0; r < 16; r++) {
            int row = w * 16 + r;
            float2 v = *(float2*)&stg[row * 68 + colp];
            size_t gr = (size_t)(r0 + row);
            const unsigned char* mp = mask + ((size_t)b * SS + gr) * SS + c0 + colg;
            v.x = mp[0] ? -1e9f : v.x * 0.125f;
            v.y = mp[1] ? -1e9f : v.y * 0.125f;
            *(float2*)(attn + ((size_t)bh * SS + gr) * SS + c0 + colg) = v;
            float mx = fmaxf(v.x, v.y);
            #pragma unroll
            for (int o = 16; o; o >>= 1) mx = fmaxf(mx, __shfl_xor_sync(0xffffffffu, mx, o));
            float s = __expf(v.x - mx) + __expf(v.y - mx);
            #pragma unroll
            for (int o = 16; o; o >>= 1) s += __shfl_xor_sync(0xffffffffu, s, o);
            if (lane == 0) {
                size_t idx = ((size_t)bh * SS + gr) * NCT + blockIdx.x;
                g_smax[idx] = mx;
                g_ssum[idx] = s;
            }
        }
    }
}

// ---------------------------------------------------------------------------
// Combine tile stats into per-row max and 1/sum. One warp per row.
// ---------------------------------------------------------------------------
__global__ __launch_bounds__(256) void softmax_stats(
    float* __restrict__ rowm, float* __restrict__ rinv)
{
    const int w = threadIdx.x >> 5, lane = threadIdx.x & 31;
    const size_t rg = (size_t)blockIdx.x * 8 + w;
    float m_l = g_smax[rg * NCT + lane];
    float s_l = g_ssum[rg * NCT + lane];
    float m = m_l;
    #pragma unroll
    for (int o = 16; o; o >>= 1) m = fmaxf(m, __shfl_xor_sync(0xffffffffu, m, o));
    float c = __expf(m_l - m) * s_l;
    #pragma unroll
    for (int o = 16; o; o >>= 1) c += __shfl_xor_sync(0xffffffffu, c, o);
    if (lane == 0) { rowm[rg] = m; rinv[rg] = 1.0f / c; }
}

// ---------------------------------------------------------------------------
// Split GEMM smem layout (shared by qkproj and template GEMM)
// ---------------------------------------------------------------------------
template<int SPLIT>
struct GOff {
    static const unsigned AH = 0;
    static const unsigned AL = 20480;
    static const unsigned WH = SPLIT ? 40960u : 20480u;
    static const unsigned WL = 50176;
    static const unsigned ABUF = 10240;
    static const unsigned WBUF = 4608;
    static const unsigned SMEM = SPLIT ? 59392u : 29696u;
};

template<int SPLIT>
__device__ __forceinline__ void gload(
    unsigned sb, int buf,
    const __nv_bfloat16* __restrict__ Ah, const __nv_bfloat16* __restrict__ Al,
    const __nv_bfloat16* __restrict__ Wh, const __nv_bfloat16* __restrict__ Wl,
    int row0, int col0, int kk, int t)
{
    #pragma unroll
    for (int i = 0; i < 2; i++) {
        int ch = t + i * 256;
        int r = ch >> 2, c = (ch & 3) * 8;
        unsigned off = buf * GOff<SPLIT>::ABUF + r * 80 + c * 2;
        cp16(sb + GOff<SPLIT>::AH + off, Ah + (size_t)(row0 + r) * 512 + kk + c);
        if (SPLIT)
            cp16(sb + GOff<SPLIT>::AL + off, Al + (size_t)(row0 + r) * 512 + kk + c);
    }
    {
        int r = t >> 3, c = (t & 7) * 8;
        unsigned off = buf * GOff<SPLIT>::WBUF + r * 144 + c * 2;
        cp16(sb + GOff<SPLIT>::WH + off, Wh + (size_t)(kk + r) * 512 + col0 + c);
        if (SPLIT)
            cp16(sb + GOff<SPLIT>::WL + off, Wl + (size_t)(kk + r) * 512 + col0 + c);
    }
}

// core split mainloop + head-major hi/lo epilogue, shared by Q/K projection
__device__ __forceinline__ void qkproj_body(
    const __nv_bfloat16* __restrict__ Ah, const __nv_bfloat16* __restrict__ Al,
    const __nv_bfloat16* __restrict__ Wh, const __nv_bfloat16* __restrict__ Wl,
    const float* __restrict__ bias,
    __nv_bfloat16* __restrict__ Oh, __nv_bfloat16* __restrict__ Ol,
    char* smem_raw)
{
    const unsigned sb = sptr(smem_raw);
    const int t = threadIdx.x, lane = t & 31, w = t >> 5;
    const int wm = w & 3, wn = w >> 2;
    const int row0 = blockIdx.y * 128, col0 = blockIdx.x * 64;

    float acc[2][4][4] = {};

    gload<1>(sb, 0, Ah, Al, Wh, Wl, row0, col0, 0, t);
    cp_commit();

    for (int it = 0; it < 16; it++) {
        if (it < 15)
            gload<1>(sb, (it + 1) & 1, Ah, Al, Wh, Wl, row0, col0, (it + 1) * 32, t);
        cp_commit();
        cp_wait1();
        __syncthreads();

        const unsigned abh = sb + GOff<1>::AH + (it & 1) * GOff<1>::ABUF;
        const unsigned abl = sb + GOff<1>::AL + (it & 1) * GOff<1>::ABUF;
        const unsigned wbh = sb + GOff<1>::WH + (it & 1) * GOff<1>::WBUF;
        const unsigned wbl = sb + GOff<1>::WL + (it & 1) * GOff<1>::WBUF;

        #pragma unroll
        for (int k2 = 0; k2 < 32; k2 += 16) {
            unsigned ah[2][4], al[2][4];
            #pragma unroll
            for (int mi = 0; mi < 2; mi++) {
                int r = wm * 32 + mi * 16 + (lane & 15);
                int c = k2 + ((lane >> 4) << 3);
                ldsm4(ah[mi], abh + r * 80 + c * 2);
                ldsm4(al[mi], abl + r * 80 + c * 2);
            }
            #pragma unroll
            for (int g = 0; g < 2; g++) {
                int kr = k2 + (lane & 7) + (((lane >> 3) & 1) << 3);
                int nc = wn * 32 + g * 16 + ((lane >> 4) << 3);
                unsigned bh_[4], bl_[4];
                ldsm4t(bh_, wbh + kr * 144 + nc * 2);
                ldsm4t(bl_, wbl + kr * 144 + nc * 2);
                #pragma unroll
                for (int mi = 0; mi < 2; mi++) {
                    mma_bf16(acc[mi][2*g],   ah[mi], &bh_[0]);
                    mma_bf16(acc[mi][2*g+1], ah[mi], &bh_[2]);
                    mma_bf16(acc[mi][2*g],   ah[mi], &bl_[0]);
                    mma_bf16(acc[mi][2*g+1], ah[mi], &bl_[2]);
                    mma_bf16(acc[mi][2*g],   al[mi], &bh_[0]);
                    mma_bf16(acc[mi][2*g+1], al[mi], &bh_[2]);
                }
            }
        }
        __syncthreads();
    }

    #pragma unroll
    for (int mi = 0; mi < 2; mi++) {
        #pragma unroll
        for (int nf = 0; nf < 4; nf++) {
            float* c = acc[mi][nf];
            int m = row0 + wm * 32 + mi * 16 + (lane >> 2);
            int n = col0 + wn * 32 + nf * 8 + ((lane & 3) << 1);
            float b0 = bias[n], b1 = bias[n + 1];
            int h = n >> 6, d = n & 63;
            int b = m >> 11, s = m & 2047;
            size_t base = ((size_t)(b * NH + h) * SS + s) * DK + d;
            __nv_bfloat162 h2, l2;
            split_pair(c[0] + b0, c[1] + b1, h2, l2);
            *(__nv_bfloat162*)&Oh[base] = h2;
            *(__nv_bfloat162*)&Ol[base] = l2;
            split_pair(c[2] + b0, c[3] + b1, h2, l2);
            *(__nv_bfloat162*)&Oh[base + 8 * (size_t)DK] = h2;
            *(__nv_bfloat162*)&Ol[base + 8 * (size_t)DK] = l2;
        }
    }
}

// Q and K projections in ONE launch: grid.z = 0 -> Q, 1 -> K.
__global__ __launch_bounds__(256, 3) void mma_qkproj(
    const float* __restrict__ bq, const float* __restrict__ bk)
{
    extern __shared__ __align__(16) char smem_raw[];
    if (blockIdx.z == 0)
        qkproj_body(g_inqh, g_inql, g_wqh, g_wql, bq, g_qh, g_ql, smem_raw);
    else
        qkproj_body(g_inkh, g_inkl, g_wkh, g_wkl, bk, g_kh, g_kl, smem_raw);
}

// ---------------------------------------------------------------------------
// Generic GEMM template (used for V-proj plain and out-proj plain)
// ---------------------------------------------------------------------------
template<int OUTPROJ, int SPLIT, int OUTLO>
__global__ __launch_bounds__(256, 3) void mma_gemm512(
    const __nv_bfloat16* __restrict__ Ah, const __nv_bfloat16* __restrict__ Al,
    const __nv_bfloat16* __restrict__ Wh, const __nv_bfloat16* __restrict__ Wl,
    const float* __restrict__ bias, const float* __restrict__ resid,
    __nv_bfloat16* __restrict__ Oh, __nv_bfloat16* __restrict__ Ol,
    float* __restrict__ Of)
{
    extern __shared__ __align__(16) char smem_raw[];
    const unsigned sb = sptr(smem_raw);
    const int t = threadIdx.x, lane = t & 31, w = t >> 5;
    const int wm = w & 3, wn = w >> 2;
    const int row0 = blockIdx.y * 128, col0 = blockIdx.x * 64;

    float acc[2][4][4] = {};

    gload<SPLIT>(sb, 0, Ah, Al, Wh, Wl, row0, col0, 0, t);
    cp_commit();

    for (int it = 0; it < 16; it++) {
        if (it < 15)
            gload<SPLIT>(sb, (it + 1) & 1, Ah, Al, Wh, Wl, row0, col0, (it + 1) * 32, t);
        cp_commit();
        cp_wait1();
        __syncthreads();

        const unsigned abh = sb + GOff<SPLIT>::AH + (it & 1) * GOff<SPLIT>::ABUF;
        const unsigned abl = sb + GOff<SPLIT>::AL + (it & 1) * GOff<SPLIT>::ABUF;
        const unsigned wbh = sb + GOff<SPLIT>::WH + (it & 1) * GOff<SPLIT>::WBUF;
        const unsigned wbl = sb + GOff<SPLIT>::WL + (it & 1) * GOff<SPLIT>::WBUF;

        #pragma unroll
        for (int k2 = 0; k2 < 32; k2 += 16) {
            unsigned ah[2][4], al[2][4];
            #pragma unroll
            for (int mi = 0; mi < 2; mi++) {
                int r = wm * 32 + mi * 16 + (lane & 15);
                int c = k2 + ((lane >> 4) << 3);
                ldsm4(ah[mi], abh + r * 80 + c * 2);
                if (SPLIT) ldsm4(al[mi], abl + r * 80 + c * 2);
            }
            #pragma unroll
            for (int g = 0; g < 2; g++) {
                int kr = k2 + (lane & 7) + (((lane >> 3) & 1) << 3);
                int nc = wn * 32 + g * 16 + ((lane >> 4) << 3);
                unsigned bh_[4], bl_[4];
                ldsm4t(bh_, wbh + kr * 144 + nc * 2);
                if (SPLIT) ldsm4t(bl_, wbl + kr * 144 + nc * 2);
                #pragma unroll
                for (int mi = 0; mi < 2; mi++) {
                    mma_bf16(acc[mi][2*g],   ah[mi], &bh_[0]);
                    mma_bf16(acc[mi][2*g+1], ah[mi], &bh_[2]);
                    if (SPLIT) {
                        mma_bf16(acc[mi][2*g],   ah[mi], &bl_[0]);
                        mma_bf16(acc[mi][2*g+1], ah[mi], &bl_[2]);
                        mma_bf16(acc[mi][2*g],   al[mi], &bh_[0]);
                        mma_bf16(acc[mi][2*g+1], al[mi], &bh_[2]);
                    }
                }
            }
        }
        __syncthreads();
    }

    #pragma unroll
    for (int mi = 0; mi < 2; mi++) {
        #pragma unroll
        for (int nf = 0; nf < 4; nf++) {
            float* c = acc[mi][nf];
            int m = row0 + wm * 32 + mi * 16 + (lane >> 2);
            int n = col0 + wn * 32 + nf * 8 + ((lane & 3) << 1);
            float b0 = bias[n], b1 = bias[n + 1];
            if (OUTPROJ) {
                float2 r = *(const float2*)(resid + (size_t)m * 512 + n);
                *(float2*)(Of + (size_t)m * 512 + n) =
                    make_float2(c[0] + b0 + r.x, c[1] + b1 + r.y);
                r = *(const float2*)(resid + (size_t)(m + 8) * 512 + n);
                *(float2*)(Of + (size_t)(m + 8) * 512 + n) =
                    make_float2(c[2] + b0 + r.x, c[3] + b1 + r.y);
            } else {
                int h = n >> 6, d = n & 63;
                int b = m >> 11, s = m & 2047;
                size_t base = ((size_t)(b * NH + h) * SS + s) * DK + d;
                if (OUTLO) {
                    __nv_bfloat162 h2, l2;
                    split_pair(c[0] + b0, c[1] + b1, h2, l2);
                    *(__nv_bfloat162*)&Oh[base] = h2;
                    *(__nv_bfloat162*)&Ol[base] = l2;
                    split_pair(c[2] + b0, c[3] + b1, h2, l2);
                    *(__nv_bfloat162*)&Oh[base + 8 * (size_t)DK] = h2;
                    *(__nv_bfloat162*)&Ol[base + 8 * (size_t)DK] = l2;
                } else {
                    *(__nv_bfloat162*)&Oh[base] =
                        __float22bfloat162_rn(make_float2(c[0] + b0, c[1] + b1));
                    *(__nv_bfloat162*)&Oh[base + 8 * (size_t)DK] =
                        __float22bfloat162_rn(make_float2(c[2] + b0, c[3] + b1));
                }
            }
        }
    }
}

// ---------------------------------------------------------------------------
// Context + softmax normalize, pure bf16 P and V. Double-buffered cp.async
// pipeline; exp/prob-write phase is row-per-warp for coalesced STG (537MB).
// (256,2) ONLY — the 80-reg (256,3) clamp spills the fused exp loop
// (rounds 6, 11). Do not retry.
// ---------------------------------------------------------------------------
#define CT_PRAW 0
#define CT_PBUF 32768                       // 128 rows * 64 floats * 4B
#define CT_PH   (2 * CT_PBUF)               // 65536; 128x72 bf16 = 18432
#define CT_VH   (CT_PH + 18432)             // 83968; 2 x 64x72 bf16
#define CT_VBUF 9216
#define CT_STAT (CT_VH + 2 * CT_VBUF)       // 102400; rowm[128]+rinv[128]
#define CT_SMEM (CT_STAT + 1024)            // 103424

__global__ __launch_bounds__(256, 2) void mma_context(
    float* __restrict__ attn, const float* __restrict__ rowm,
    const float* __restrict__ rinv, __nv_bfloat16* __restrict__ ctxh)
{
    extern __shared__ __align__(16) char smem_raw[];
    const unsigned sb = sptr(smem_raw);
    __nv_bfloat16 (*Ph)[72] = (__nv_bfloat16(*)[72])(smem_raw + CT_PH);
    float* s_rowm = (float*)(smem_raw + CT_STAT);
    float* s_rinv = s_rowm + 128;

    const int t = threadIdx.x, lane = t & 31, w = t >> 5;
    const int wm = w & 3, wn = w >> 2;
    const int bh = blockIdx.y, r0 = blockIdx.x * 128;
    const size_t vbase = (size_t)bh * SS * DK;
    float* arow_base = attn + (size_t)bh * SS * SS + (size_t)r0 * SS;

    if (t < 128) {
        s_rowm[t] = rowm[(size_t)bh * SS + r0 + t];
        s_rinv[t] = rinv[(size_t)bh * SS + r0 + t];
    }

    float acc[2][4][4] = {};

    // chunk loader: raw P (128x64 fp32, 256B rows) + V (64x64 bf16)
    #define CT_LOAD(kk, buf) do {                                              \
        unsigned pb = sb + CT_PRAW + (buf) * CT_PBUF;                          \
        _Pragma("unroll")                                                      \
        for (int i = 0; i < 8; i++) {                                          \
            int ch = t + i * 256;                                              \
            int row = ch >> 4, seg = ch & 15;                                  \
            cp16(pb + row * 256 + seg * 16,                                    \
                 arow_base + (size_t)row * SS + (kk) + seg * 4);               \
        }                                                                      \
        unsigned vb = sb + CT_VH + (buf) * CT_VBUF;                            \
        _Pragma("unroll")                                                      \
        for (int i = 0; i < 2; i++) {                                          \
            int idx = t + i * 256;                                             \
            int vr = idx >> 3, vc = (idx & 7) * 8;                             \
            cp16(vb + vr * 144 + vc * 2,                                       \
                 g_vh + vbase + (size_t)((kk) + vr) * 64 + vc);                \
        }                                                                      \
    } while (0)

    CT_LOAD(0, 0);
    cp_commit();

    for (int it = 0; it < 32; it++) {
        const int buf = it & 1;
        if (it < 31) CT_LOAD((it + 1) * 64, buf ^ 1);
        cp_commit();
        cp_wait1();            // current chunk's group complete
        __syncthreads();

        {   // exp/normalize + coalesced prob write: warp w -> rows w*16..+15
            const float* praw = (const float*)(smem_raw + CT_PRAW + buf * CT_PBUF);
            #pragma unroll 4
            for (int r = 0; r < 16; r++) {
                int row = w * 16 + r;
                float m_ = s_rowm[row], ri_ = s_rinv[row];
                float2 v = *(const float2*)&praw[row * 64 + lane * 2];
                v.x = __expf(v.x - m_) * ri_;
                v.y = __expf(v.y - m_) * ri_;
                *(float2*)(arow_base + (size_t)row * SS + it * 64 + lane * 2) = v;
                *(__nv_bfloat162*)&Ph[row][lane * 2] =
                    __float22bfloat162_rn(v);
            }
        }
        __syncthreads();

        const unsigned vb = sb + CT_VH + buf * CT_VBUF;
        #pragma unroll
        for (int k2 = 0; k2 < 64; k2 += 16) {
            unsigned ah[2][4];
            #pragma unroll
            for (int mi = 0; mi < 2; mi++) {
                int r = wm * 32 + mi * 16 + (lane & 15);
                int c = k2 + ((lane >> 4) << 3);
                ldsm4(ah[mi], sptr(&Ph[r][c]));
            }
            #pragma unroll
            for (int g = 0; g < 2; g++) {
                int kr = k2 + (lane & 7) + (((lane >> 3) & 1) << 3);
                int nc = wn * 32 + g * 16 + ((lane >> 4) << 3);
                unsigned bh_[4];
                ldsm4t(bh_, vb + kr * 144 + nc * 2);
                #pragma unroll
                for (int mi = 0; mi < 2; mi++) {
                    mma_bf16(acc[mi][2*g],   ah[mi], &bh_[0]);
                    mma_bf16(acc[mi][2*g+1], ah[mi], &bh_[2]);
                }
            }
        }
        __syncthreads();
    }
    #undef CT_LOAD

    const int b = bh >> 3, h = bh & 7;
    #pragma unroll
    for (int mi = 0; mi < 2; mi++) {
        #pragma unroll
        for (int nf = 0; nf < 4; nf++) {
            float* c = acc[mi][nf];
            int m = r0 + wm * 32 + mi * 16 + (lane >> 2);
            int n = wn * 32 + nf * 8 + ((lane & 3) << 1);
            size_t idx = ((size_t)(b * SS + m)) * EMB + h * DK + n;
            *(__nv_bfloat162*)&ctxh[idx] =
                __float22bfloat162_rn(make_float2(c[0], c[1]));
            *(__nv_bfloat162*)&ctxh[idx + 8 * (size_t)EMB] =
                __float22bfloat162_rn(make_float2(c[2], c[3]));
        }
    }
}

// ---------------------------------------------------------------------------
// LayerNorm over 512.
// ---------------------------------------------------------------------------
__global__ __launch_bounds__(128) void ln_kernel(
    const float* __restrict__ gamma, const float* __restrict__ beta,
    float* __restrict__ out)
{
    const size_t row = blockIdx.x;
    const int t = threadIdx.x;
    const float* x = g_x + row * EMB;
    __shared__ float rs[4], rq[4];

    float4 v = ((const float4*)x)[t];
    float s  = v.x + v.y + v.z + v.w;
    float sq = v.x*v.x + v.y*v.y + v.z*v.z + v.w*v.w;
    #pragma unroll
    for (int o = 16; o; o >>= 1) {
        s  += __shfl_xor_sync(0xffffffffu, s,  o);
        sq += __shfl_xor_sync(0xffffffffu, sq, o);
    }
    if ((t & 31) == 0) { rs[t >> 5] = s; rq[t >> 5] = sq; }
    __syncthreads();
    s  = rs[0] + rs[1] + rs[2] + rs[3];
    sq = rq[0] + rq[1] + rq[2] + rq[3];

    float mu  = s * (1.0f / 512.0f);
    float var = sq * (1.0f / 512.0f) - mu * mu;
    float inv = rsqrtf(var + 1e-5f);

    float4 g = ((const float4*)gamma)[t];
    float4 bb = ((const float4*)beta)[t];
    float4 o;
    o.x = (v.x - mu) * inv * g.x + bb.x;
    o.y = (v.y - mu) * inv * g.y + bb.y;
    o.z = (v.z - mu) * inv * g.z + bb.z;
    o.w = (v.w - mu) * inv * g.w + bb.w;
    ((float4*)(out + row * EMB))[t] = o;
}

// ---------------------------------------------------------------------------
extern "C" void kernel_launch(void* const* d_in, const int* in_sizes, int n_in,
                              void* d_out, int out_size)
{
    const float* Q  = (const float*)d_in[0];
    const float* K  = (const float*)d_in[1];
    const float* V  = (const float*)d_in[2];
    const unsigned char* mask = (const unsigned char*)d_in[3];
    const float* Wq = (const float*)d_in[4];
    const float* bq = (const float*)d_in[5];
    const float* Wk = (const float*)d_in[6];
    const float* bk = (const float*)d_in[7];
    const float* Wv = (const float*)d_in[8];
    const float* bv = (const float*)d_in[9];
    const float* Wo = (const float*)d_in[10];
    const float* bo = (const float*)d_in[11];
    const float* gamma = (const float*)d_in[12];
    const float* beta  = (const float*)d_in[13];

    float* out  = (float*)d_out;
    float* attn = out + (size_t)BSROWS * EMB;

    __nv_bfloat16 *invh, *wvh, *woh, *vh, *ctxh;
    float *xp, *rowmp, *rinvp;
    cudaGetSymbolAddress((void**)&invh, g_invh);
    cudaGetSymbolAddress((void**)&wvh, g_wvh);
    cudaGetSymbolAddress((void**)&woh, g_woh);
    cudaGetSymbolAddress((void**)&vh, g_vh);
    cudaGetSymbolAddress((void**)&ctxh, g_ctxh);
    cudaGetSymbolAddress((void**)&xp,   g_x);
    cudaGetSymbolAddress((void**)&rowmp, g_rowm);
    cudaGetSymbolAddress((void**)&rinvp, g_rinv);

    cudaFuncSetAttribute(mma_scores, cudaFuncAttributeMaxDynamicSharedMemorySize,
                         SC_SMEM);
    cudaFuncSetAttribute(mma_qkproj, cudaFuncAttributeMaxDynamicSharedMemorySize,
                         GOff<1>::SMEM);
    cudaFuncSetAttribute(mma_gemm512<0,0,0>, cudaFuncAttributeMaxDynamicSharedMemorySize,
                         GOff<0>::SMEM);
    cudaFuncSetAttribute(mma_gemm512<1,0,0>, cudaFuncAttributeMaxDynamicSharedMemorySize,
                         GOff<0>::SMEM);
    cudaFuncSetAttribute(mma_context, cudaFuncAttributeMaxDynamicSharedMemorySize,
                         CT_SMEM);

    // merged conversions
    const int n4_in = BSROWS * EMB / 4;       // 1,048,576
    const int n4_w  = EMB * EMB / 4;          // 65,536
    const int nblk_in = (n4_in * 3 + 255) / 256;   // 12288
    const int nblk_w  = (n4_w * 4 + 255) / 256;    // 1024
    convert_all<<<nblk_in + nblk_w, 256>>>(Q, K, V, Wq, Wk, Wv, Wo,
                                           n4_in, nblk_in, n4_w);

    // Q + K projections in one launch (z = 0/1), then V projection
    dim3 qk_grid(EMB / 64, BSROWS / 128, 2);       // 8 x 64 x 2
    mma_qkproj<<<qk_grid, 256, GOff<1>::SMEM>>>(bq, bk);

    dim3 gemm_grid(EMB / 64, BSROWS / 128);        // 8 x 64
    mma_gemm512<0,0,0><<<gemm_grid, 256, GOff<0>::SMEM>>>(
        invh, nullptr, wvh, nullptr, bv, nullptr, vh, nullptr, nullptr);

    dim3 sc_grid(SS / 64, SS / 128, BH);           // 32 x 16 x 32
    mma_scores<<<sc_grid, 256, SC_SMEM>>>(mask, attn);

    softmax_stats<<<(BH * SS) / 8, 256>>>(rowmp, rinvp);

    dim3 ctx_grid(SS / 128, BH);                   // 16 x 32
    mma_context<<<ctx_grid, 256, CT_SMEM>>>(attn, rowmp, rinvp, ctxh);

    mma_gemm512<1,0,0><<<gemm_grid, 256, GOff<0>::SMEM>>>(
        ctxh, nullptr, woh, nullptr, bo, Q, nullptr, nullptr, xp);

    ln_kernel<<<BSROWS, 128>>>(gamma, beta, out);
}

// round 16
// speedup vs baseline: 1.8242x; 1.0447x over previous
#include <cuda_runtime.h>
#include <cuda_bf16.h>
#include <math.h>

#define BB   4
#define SS   2048
#define EMB  512
#define NH   8
#define DK   64
#define BSROWS (BB*SS)   // 8192
#define BH   (BB*NH)     // 32
#define NCT  (SS/64)     // 32 col tiles in scores

// projection outputs
__device__ __nv_bfloat16 g_qh[BH * SS * DK];
__device__ __nv_bfloat16 g_ql[BH * SS * DK];
__device__ __nv_bfloat16 g_kh[BH * SS * DK];
__device__ __nv_bfloat16 g_kl[BH * SS * DK];
__device__ __nv_bfloat16 g_vh[BH * SS * DK];       // plain bf16 (precision budget)
// pre-split / pre-converted inputs
__device__ __nv_bfloat16 g_inqh[BSROWS * EMB], g_inql[BSROWS * EMB];
__device__ __nv_bfloat16 g_inkh[BSROWS * EMB], g_inkl[BSROWS * EMB];
__device__ __nv_bfloat16 g_invh[BSROWS * EMB];
// weights
__device__ __nv_bfloat16 g_wqh[EMB * EMB], g_wql[EMB * EMB];
__device__ __nv_bfloat16 g_wkh[EMB * EMB], g_wkl[EMB * EMB];
__device__ __nv_bfloat16 g_wvh[EMB * EMB];
__device__ __nv_bfloat16 g_woh[EMB * EMB];
// context (plain bf16) + pre-LN sum
__device__ __nv_bfloat16 g_ctxh[BSROWS * EMB];
__device__ float g_x[BSROWS * EMB];
// softmax stats
__device__ float g_smax[(size_t)BH * SS * NCT];
__device__ float g_ssum[(size_t)BH * SS * NCT];
__device__ float g_rowm[(size_t)BH * SS];
__device__ float g_rinv[(size_t)BH * SS];

// ---------------------------------------------------------------------------
// helpers
// ---------------------------------------------------------------------------
__device__ __forceinline__ unsigned sptr(const void* p) {
    return (unsigned)__cvta_generic_to_shared(p);
}
__device__ __forceinline__ void ldsm4(unsigned* r, unsigned a) {
    asm volatile("ldmatrix.sync.aligned.m8n8.x4.shared.b16 {%0,%1,%2,%3}, [%4];"
                 : "=r"(r[0]), "=r"(r[1]), "=r"(r[2]), "=r"(r[3]) : "r"(a));
}
__device__ __forceinline__ void ldsm4t(unsigned* r, unsigned a) {
    asm volatile("ldmatrix.sync.aligned.m8n8.x4.trans.shared.b16 {%0,%1,%2,%3}, [%4];"
                 : "=r"(r[0]), "=r"(r[1]), "=r"(r[2]), "=r"(r[3]) : "r"(a));
}
__device__ __forceinline__ void mma_bf16(float* c, const unsigned* a, const unsigned* b) {
    asm volatile(
        "mma.sync.aligned.m16n8k16.row.col.f32.bf16.bf16.f32 "
        "{%0,%1,%2,%3},{%4,%5,%6,%7},{%8,%9},{%0,%1,%2,%3};"
        : "+f"(c[0]), "+f"(c[1]), "+f"(c[2]), "+f"(c[3])
        : "r"(a[0]), "r"(a[1]), "r"(a[2]), "r"(a[3]), "r"(b[0]), "r"(b[1]));
}
__device__ __forceinline__ void split_pair(float x, float y,
                                           __nv_bfloat162& h2, __nv_bfloat162& l2) {
    __nv_bfloat16 hx = __float2bfloat16_rn(x);
    __nv_bfloat16 hy = __float2bfloat16_rn(y);
    __nv_bfloat16 lx = __float2bfloat16_rn(x - __bfloat162float(hx));
    __nv_bfloat16 ly = __float2bfloat16_rn(y - __bfloat162float(hy));
    h2 = __halves2bfloat162(hx, hy);
    l2 = __halves2bfloat162(lx, ly);
}
__device__ __forceinline__ void cp16(unsigned dst, const void* src) {
    asm volatile("cp.async.cg.shared.global [%0], [%1], 16;" :: "r"(dst), "l"(src));
}
__device__ __forceinline__ void cp_commit() {
    asm volatile("cp.async.commit_group;");
}
__device__ __forceinline__ void cp_wait0() {
    asm volatile("cp.async.wait_group 0;");
}
__device__ __forceinline__ void cp_wait1() {
    asm volatile("cp.async.wait_group 1;");
}

// ---------------------------------------------------------------------------
// Merged conversions: inputs (Q,K hi/lo; V hi) then weights (Wq,Wk hi/lo;
// Wv,Wo hi) in a single launch.
// ---------------------------------------------------------------------------
__global__ __launch_bounds__(256) void convert_all(
    const float* __restrict__ Q, const float* __restrict__ K,
    const float* __restrict__ V,
    const float* __restrict__ Wq, const float* __restrict__ Wk,
    const float* __restrict__ Wv, const float* __restrict__ Wo,
    int n4_in, int nblk_in, int n4_w)
{
    if ((int)blockIdx.x < nblk_in) {
        int i = blockIdx.x * blockDim.x + threadIdx.x;
        if (i >= n4_in * 3) return;
        int which = i / n4_in, j = i - which * n4_in;
        const float* in = which == 0 ? Q : which == 1 ? K : V;
        float4 v = ((const float4*)in)[j];
        __nv_bfloat162 h2, l2, h3, l3;
        split_pair(v.x, v.y, h2, l2);
        split_pair(v.z, v.w, h3, l3);
        __nv_bfloat16* hi = which == 0 ? g_inqh : which == 1 ? g_inkh : g_invh;
        ((__nv_bfloat162*)hi)[j * 2]     = h2;
        ((__nv_bfloat162*)hi)[j * 2 + 1] = h3;
        if (which < 2) {
            __nv_bfloat16* lo = which == 0 ? g_inql : g_inkl;
            ((__nv_bfloat162*)lo)[j * 2]     = l2;
            ((__nv_bfloat162*)lo)[j * 2 + 1] = l3;
        }
    } else {
        int i = (blockIdx.x - nblk_in) * blockDim.x + threadIdx.x;
        if (i >= n4_w * 4) return;
        int which = i / n4_w, j = i - which * n4_w;
        const float* in = which == 0 ? Wq : which == 1 ? Wk : which == 2 ? Wv : Wo;
        float4 v = ((const float4*)in)[j];
        __nv_bfloat162 h2, l2, h3, l3;
        split_pair(v.x, v.y, h2, l2);
        split_pair(v.z, v.w, h3, l3);
        __nv_bfloat16* hi = which == 0 ? g_wqh : which == 1 ? g_wkh
                          : which == 2 ? g_wvh : g_woh;
        ((__nv_bfloat162*)hi)[j * 2]     = h2;
        ((__nv_bfloat162*)hi)[j * 2 + 1] = h3;
        if (which < 2) {
            __nv_bfloat16* lo = which == 0 ? g_wql : g_wkl;
            ((__nv_bfloat162*)lo)[j * 2]     = l2;
            ((__nv_bfloat162*)lo)[j * 2 + 1] = l3;
        }
    }
}

// ---------------------------------------------------------------------------
// Scores: per (b,h) 128x64 tile of q @ k^T * 0.125, masked, fp32 to attn.
// Split (3-product) MMA; coalesced smem-restaged epilogue. Row stats via
// thread-per-half-row serial reduction (2 shfl/row total). float2 LDS only:
// half-row offsets are 8B- but not 16B-aligned (round-15 misaligned-addr).
// ---------------------------------------------------------------------------
#define SC_QH 0
#define SC_QL 18432
#define SC_KH 36864
#define SC_KL 46080
#define SC_SMEM 55296

__global__ __launch_bounds__(256, 3) void mma_scores(
    const unsigned char* __restrict__ mask, float* __restrict__ attn)
{
    extern __shared__ __align__(16) char smem_raw[];
    __nv_bfloat16 (*Qh)[72] = (__nv_bfloat16(*)[72])(smem_raw + SC_QH);
    __nv_bfloat16 (*Ql)[72] = (__nv_bfloat16(*)[72])(smem_raw + SC_QL);
    __nv_bfloat16 (*Kh)[72] = (__nv_bfloat16(*)[72])(smem_raw + SC_KH);
    __nv_bfloat16 (*Kl)[72] = (__nv_bfloat16(*)[72])(smem_raw + SC_KL);

    const int t = threadIdx.x, lane = t & 31, w = t >> 5;
    const int wm = w & 3, wn = w >> 2;
    const int bh = blockIdx.z, b = bh >> 3;
    const int r0 = blockIdx.y * 128, c0 = blockIdx.x * 64;
    const size_t base = (size_t)bh * SS * DK;

    #pragma unroll
    for (int i = 0; i < 12; i++) {
        int ch = t + i * 256;
        if (ch < 1024) {
            int r = ch >> 3, c8 = (ch & 7) * 8;
            cp16(sptr(&Qh[r][c8]), g_qh + base + (size_t)(r0 + r) * 64 + c8);
        } else if (ch < 2048) {
            int idx = ch - 1024, r = idx >> 3, c8 = (idx & 7) * 8;
            cp16(sptr(&Ql[r][c8]), g_ql + base + (size_t)(r0 + r) * 64 + c8);
        } else if (ch < 2560) {
            int idx = ch - 2048, r = idx >> 3, c8 = (idx & 7) * 8;
            cp16(sptr(&Kh[r][c8]), g_kh + base + (size_t)(c0 + r) * 64 + c8);
        } else {
            int idx = ch - 2560, r = idx >> 3, c8 = (idx & 7) * 8;
            cp16(sptr(&Kl[r][c8]), g_kl + base + (size_t)(c0 + r) * 64 + c8);
        }
    }
    cp_commit();
    cp_wait0();
    __syncthreads();

    float acc[2][4][4] = {};
    #pragma unroll
    for (int k2 = 0; k2 < 64; k2 += 16) {
        unsigned ah[2][4], al[2][4];
        #pragma unroll
        for (int mi = 0; mi < 2; mi++) {
            int r = wm * 32 + mi * 16 + (lane & 15);
            int c = k2 + ((lane >> 4) << 3);
            ldsm4(ah[mi], sptr(&Qh[r][c]));
            ldsm4(al[mi], sptr(&Ql[r][c]));
        }
        #pragma unroll
        for (int g = 0; g < 2; g++) {
            int nr = wn * 32 + g * 16 + (lane & 7) + ((lane >> 4) << 3);
            int kc = k2 + (((lane >> 3) & 1) << 3);
            unsigned bh_[4], bl_[4];
            ldsm4(bh_, sptr(&Kh[nr][kc]));
            ldsm4(bl_, sptr(&Kl[nr][kc]));
            #pragma unroll
            for (int mi = 0; mi < 2; mi++) {
                mma_bf16(acc[mi][2*g],   ah[mi], &bh_[0]);
                mma_bf16(acc[mi][2*g+1], ah[mi], &bh_[2]);
                mma_bf16(acc[mi][2*g],   ah[mi], &bl_[0]);
                mma_bf16(acc[mi][2*g+1], ah[mi], &bl_[2]);
                mma_bf16(acc[mi][2*g],   al[mi], &bh_[0]);
                mma_bf16(acc[mi][2*g+1], al[mi], &bh_[2]);
            }
        }
    }

    // restage through smem: [128][68] fp32, halves at col offsets 0/34
    __syncthreads();
    float* stg = (float*)smem_raw;
    #pragma unroll
    for (int mi = 0; mi < 2; mi++) {
        #pragma unroll
        for (int nf = 0; nf < 4; nf++) {
            float* c = acc[mi][nf];
            int r = wm * 32 + mi * 16 + (lane >> 2);
            int cc = wn * 34 + nf * 8 + (lane & 3) * 2;
            *(float2*)&stg[r * 68 + cc]       = make_float2(c[0], c[1]);
            *(float2*)&stg[(r + 8) * 68 + cc] = make_float2(c[2], c[3]);
        }
    }
    __syncthreads();

    // mask + scale + coalesced STG; masked values written back to stg
    {
        const int colg = lane * 2;
        const int colp = colg + (lane >= 16 ? 2 : 0);
        #pragma unroll 4
        for (int r = 0; r < 16; r++) {
            int row = w * 16 + r;
            float2 v = *(float2*)&stg[row * 68 + colp];
            size_t gr = (size_t)(r0 + row);
            const unsigned char* mp = mask + ((size_t)b * SS + gr) * SS + c0 + colg;
            v.x = mp[0] ? -1e9f : v.x * 0.125f;
            v.y = mp[1] ? -1e9f : v.y * 0.125f;
            *(float2*)(attn + ((size_t)bh * SS + gr) * SS + c0 + colg) = v;
            *(float2*)&stg[row * 68 + colp] = v;
        }
    }
    __syncthreads();

    // stats: one thread per half-row, serial reduce + 2 shfl with partner.
    // float2 LDS only (half offsets are 8B-aligned, NOT 16B — see r15 bug).
    {
        int row = t >> 1, half = t & 1;
        const float* p = &stg[row * 68 + half * 34];
        float mx = -1e30f;
        float vbuf[32];
        #pragma unroll
        for (int i = 0; i < 16; i++) {
            float2 v = *(const float2*)(p + i * 2);
            vbuf[i*2+0] = v.x; vbuf[i*2+1] = v.y;
            mx = fmaxf(mx, fmaxf(v.x, v.y));
        }
        mx = fmaxf(mx, __shfl_xor_sync(0xffffffffu, mx, 1));   // row max
        float s = 0.f;
        #pragma unroll
        for (int i = 0; i < 32; i++) s += __expf(vbuf[i] - mx);
        s += __shfl_xor_sync(0xffffffffu, s, 1);               // row sum
        if (half == 0) {
            size_t idx = ((size_t)bh * SS + r0 + row) * NCT + blockIdx.x;
            g_smax[idx] = mx;
            g_ssum[idx] = s;
        }
    }
}

// ---------------------------------------------------------------------------
// Combine tile stats into per-row max and 1/sum. One warp per row.
// ---------------------------------------------------------------------------
__global__ __launch_bounds__(256) void softmax_stats(
    float* __restrict__ rowm, float* __restrict__ rinv)
{
    const int w = threadIdx.x >> 5, lane = threadIdx.x & 31;
    const size_t rg = (size_t)blockIdx.x * 8 + w;
    float m_l = g_smax[rg * NCT + lane];
    float s_l = g_ssum[rg * NCT + lane];
    float m = m_l;
    #pragma unroll
    for (int o = 16; o; o >>= 1) m = fmaxf(m, __shfl_xor_sync(0xffffffffu, m, o));
    float c = __expf(m_l - m) * s_l;
    #pragma unroll
    for (int o = 16; o; o >>= 1) c += __shfl_xor_sync(0xffffffffu, c, o);
    if (lane == 0) { rowm[rg] = m; rinv[rg] = 1.0f / c; }
}

// ---------------------------------------------------------------------------
// Split GEMM smem layout (shared by qkproj and template GEMM)
// ---------------------------------------------------------------------------
template<int SPLIT>
struct GOff {
    static const unsigned AH = 0;
    static const unsigned AL = 20480;
    static const unsigned WH = SPLIT ? 40960u : 20480u;
    static const unsigned WL = 50176;
    static const unsigned ABUF = 10240;
    static const unsigned WBUF = 4608;
    static const unsigned SMEM = SPLIT ? 59392u : 29696u;
};

template<int SPLIT>
__device__ __forceinline__ void gload(
    unsigned sb, int buf,
    const __nv_bfloat16* __restrict__ Ah, const __nv_bfloat16* __restrict__ Al,
    const __nv_bfloat16* __restrict__ Wh, const __nv_bfloat16* __restrict__ Wl,
    int row0, int col0, int kk, int t)
{
    #pragma unroll
    for (int i = 0; i < 2; i++) {
        int ch = t + i * 256;
        int r = ch >> 2, c = (ch & 3) * 8;
        unsigned off = buf * GOff<SPLIT>::ABUF + r * 80 + c * 2;
        cp16(sb + GOff<SPLIT>::AH + off, Ah + (size_t)(row0 + r) * 512 + kk + c);
        if (SPLIT)
            cp16(sb + GOff<SPLIT>::AL + off, Al + (size_t)(row0 + r) * 512 + kk + c);
    }
    {
        int r = t >> 3, c = (t & 7) * 8;
        unsigned off = buf * GOff<SPLIT>::WBUF + r * 144 + c * 2;
        cp16(sb + GOff<SPLIT>::WH + off, Wh + (size_t)(kk + r) * 512 + col0 + c);
        if (SPLIT)
            cp16(sb + GOff<SPLIT>::WL + off, Wl + (size_t)(kk + r) * 512 + col0 + c);
    }
}

// core split mainloop + head-major hi/lo epilogue, shared by Q/K projection
__device__ __forceinline__ void qkproj_body(
    const __nv_bfloat16* __restrict__ Ah, const __nv_bfloat16* __restrict__ Al,
    const __nv_bfloat16* __restrict__ Wh, const __nv_bfloat16* __restrict__ Wl,
    const float* __restrict__ bias,
    __nv_bfloat16* __restrict__ Oh, __nv_bfloat16* __restrict__ Ol,
    char* smem_raw)
{
    const unsigned sb = sptr(smem_raw);
    const int t = threadIdx.x, lane = t & 31, w = t >> 5;
    const int wm = w & 3, wn = w >> 2;
    const int row0 = blockIdx.y * 128, col0 = blockIdx.x * 64;

    float acc[2][4][4] = {};

    gload<1>(sb, 0, Ah, Al, Wh, Wl, row0, col0, 0, t);
    cp_commit();

    for (int it = 0; it < 16; it++) {
        if (it < 15)
            gload<1>(sb, (it + 1) & 1, Ah, Al, Wh, Wl, row0, col0, (it + 1) * 32, t);
        cp_commit();
        cp_wait1();
        __syncthreads();

        const unsigned abh = sb + GOff<1>::AH + (it & 1) * GOff<1>::ABUF;
        const unsigned abl = sb + GOff<1>::AL + (it & 1) * GOff<1>::ABUF;
        const unsigned wbh = sb + GOff<1>::WH + (it & 1) * GOff<1>::WBUF;
        const unsigned wbl = sb + GOff<1>::WL + (it & 1) * GOff<1>::WBUF;

        #pragma unroll
        for (int k2 = 0; k2 < 32; k2 += 16) {
            unsigned ah[2][4], al[2][4];
            #pragma unroll
            for (int mi = 0; mi < 2; mi++) {
                int r = wm * 32 + mi * 16 + (lane & 15);
                int c = k2 + ((lane >> 4) << 3);
                ldsm4(ah[mi], abh + r * 80 + c * 2);
                ldsm4(al[mi], abl + r * 80 + c * 2);
            }
            #pragma unroll
            for (int g = 0; g < 2; g++) {
                int kr = k2 + (lane & 7) + (((lane >> 3) & 1) << 3);
                int nc = wn * 32 + g * 16 + ((lane >> 4) << 3);
                unsigned bh_[4], bl_[4];
                ldsm4t(bh_, wbh + kr * 144 + nc * 2);
                ldsm4t(bl_, wbl + kr * 144 + nc * 2);
                #pragma unroll
                for (int mi = 0; mi < 2; mi++) {
                    mma_bf16(acc[mi][2*g],   ah[mi], &bh_[0]);
                    mma_bf16(acc[mi][2*g+1], ah[mi], &bh_[2]);
                    mma_bf16(acc[mi][2*g],   ah[mi], &bl_[0]);
                    mma_bf16(acc[mi][2*g+1], ah[mi], &bl_[2]);
                    mma_bf16(acc[mi][2*g],   al[mi], &bh_[0]);
                    mma_bf16(acc[mi][2*g+1], al[mi], &bh_[2]);
                }
            }
        }
        __syncthreads();
    }

    #pragma unroll
    for (int mi = 0; mi < 2; mi++) {
        #pragma unroll
        for (int nf = 0; nf < 4; nf++) {
            float* c = acc[mi][nf];
            int m = row0 + wm * 32 + mi * 16 + (lane >> 2);
            int n = col0 + wn * 32 + nf * 8 + ((lane & 3) << 1);
            float b0 = bias[n], b1 = bias[n + 1];
            int h = n >> 6, d = n & 63;
            int b = m >> 11, s = m & 2047;
            size_t base = ((size_t)(b * NH + h) * SS + s) * DK + d;
            __nv_bfloat162 h2, l2;
            split_pair(c[0] + b0, c[1] + b1, h2, l2);
            *(__nv_bfloat162*)&Oh[base] = h2;
            *(__nv_bfloat162*)&Ol[base] = l2;
            split_pair(c[2] + b0, c[3] + b1, h2, l2);
            *(__nv_bfloat162*)&Oh[base + 8 * (size_t)DK] = h2;
            *(__nv_bfloat162*)&Ol[base + 8 * (size_t)DK] = l2;
        }
    }
}

// Q and K projections in ONE launch: grid.z = 0 -> Q, 1 -> K.
__global__ __launch_bounds__(256, 3) void mma_qkproj(
    const float* __restrict__ bq, const float* __restrict__ bk)
{
    extern __shared__ __align__(16) char smem_raw[];
    if (blockIdx.z == 0)
        qkproj_body(g_inqh, g_inql, g_wqh, g_wql, bq, g_qh, g_ql, smem_raw);
    else
        qkproj_body(g_inkh, g_inkl, g_wkh, g_wkl, bk, g_kh, g_kl, smem_raw);
}

// ---------------------------------------------------------------------------
// Generic GEMM template (used for V-proj plain and out-proj plain)
// ---------------------------------------------------------------------------
template<int OUTPROJ, int SPLIT, int OUTLO>
__global__ __launch_bounds__(256, 3) void mma_gemm512(
    const __nv_bfloat16* __restrict__ Ah, const __nv_bfloat16* __restrict__ Al,
    const __nv_bfloat16* __restrict__ Wh, const __nv_bfloat16* __restrict__ Wl,
    const float* __restrict__ bias, const float* __restrict__ resid,
    __nv_bfloat16* __restrict__ Oh, __nv_bfloat16* __restrict__ Ol,
    float* __restrict__ Of)
{
    extern __shared__ __align__(16) char smem_raw[];
    const unsigned sb = sptr(smem_raw);
    const int t = threadIdx.x, lane = t & 31, w = t >> 5;
    const int wm = w & 3, wn = w >> 2;
    const int row0 = blockIdx.y * 128, col0 = blockIdx.x * 64;

    float acc[2][4][4] = {};

    gload<SPLIT>(sb, 0, Ah, Al, Wh, Wl, row0, col0, 0, t);
    cp_commit();

    for (int it = 0; it < 16; it++) {
        if (it < 15)
            gload<SPLIT>(sb, (it + 1) & 1, Ah, Al, Wh, Wl, row0, col0, (it + 1) * 32, t);
        cp_commit();
        cp_wait1();
        __syncthreads();

        const unsigned abh = sb + GOff<SPLIT>::AH + (it & 1) * GOff<SPLIT>::ABUF;
        const unsigned abl = sb + GOff<SPLIT>::AL + (it & 1) * GOff<SPLIT>::ABUF;
        const unsigned wbh = sb + GOff<SPLIT>::WH + (it & 1) * GOff<SPLIT>::WBUF;
        const unsigned wbl = sb + GOff<SPLIT>::WL + (it & 1) * GOff<SPLIT>::WBUF;

        #pragma unroll
        for (int k2 = 0; k2 < 32; k2 += 16) {
            unsigned ah[2][4], al[2][4];
            #pragma unroll
            for (int mi = 0; mi < 2; mi++) {
                int r = wm * 32 + mi * 16 + (lane & 15);
                int c = k2 + ((lane >> 4) << 3);
                ldsm4(ah[mi], abh + r * 80 + c * 2);
                if (SPLIT) ldsm4(al[mi], abl + r * 80 + c * 2);
            }
            #pragma unroll
            for (int g = 0; g < 2; g++) {
                int kr = k2 + (lane & 7) + (((lane >> 3) & 1) << 3);
                int nc = wn * 32 + g * 16 + ((lane >> 4) << 3);
                unsigned bh_[4], bl_[4];
                ldsm4t(bh_, wbh + kr * 144 + nc * 2);
                if (SPLIT) ldsm4t(bl_, wbl + kr * 144 + nc * 2);
                #pragma unroll
                for (int mi = 0; mi < 2; mi++) {
                    mma_bf16(acc[mi][2*g],   ah[mi], &bh_[0]);
                    mma_bf16(acc[mi][2*g+1], ah[mi], &bh_[2]);
                    if (SPLIT) {
                        mma_bf16(acc[mi][2*g],   ah[mi], &bl_[0]);
                        mma_bf16(acc[mi][2*g+1], ah[mi], &bl_[2]);
                        mma_bf16(acc[mi][2*g],   al[mi], &bh_[0]);
                        mma_bf16(acc[mi][2*g+1], al[mi], &bh_[2]);
                    }
                }
            }
        }
        __syncthreads();
    }

    #pragma unroll
    for (int mi = 0; mi < 2; mi++) {
        #pragma unroll
        for (int nf = 0; nf < 4; nf++) {
            float* c = acc[mi][nf];
            int m = row0 + wm * 32 + mi * 16 + (lane >> 2);
            int n = col0 + wn * 32 + nf * 8 + ((lane & 3) << 1);
            float b0 = bias[n], b1 = bias[n + 1];
            if (OUTPROJ) {
                float2 r = *(const float2*)(resid + (size_t)m * 512 + n);
                *(float2*)(Of + (size_t)m * 512 + n) =
                    make_float2(c[0] + b0 + r.x, c[1] + b1 + r.y);
                r = *(const float2*)(resid + (size_t)(m + 8) * 512 + n);
                *(float2*)(Of + (size_t)(m + 8) * 512 + n) =
                    make_float2(c[2] + b0 + r.x, c[3] + b1 + r.y);
            } else {
                int h = n >> 6, d = n & 63;
                int b = m >> 11, s = m & 2047;
                size_t base = ((size_t)(b * NH + h) * SS + s) * DK + d;
                if (OUTLO) {
                    __nv_bfloat162 h2, l2;
                    split_pair(c[0] + b0, c[1] + b1, h2, l2);
                    *(__nv_bfloat162*)&Oh[base] = h2;
                    *(__nv_bfloat162*)&Ol[base] = l2;
                    split_pair(c[2] + b0, c[3] + b1, h2, l2);
                    *(__nv_bfloat162*)&Oh[base + 8 * (size_t)DK] = h2;
                    *(__nv_bfloat162*)&Ol[base + 8 * (size_t)DK] = l2;
                } else {
                    *(__nv_bfloat162*)&Oh[base] =
                        __float22bfloat162_rn(make_float2(c[0] + b0, c[1] + b1));
                    *(__nv_bfloat162*)&Oh[base + 8 * (size_t)DK] =
                        __float22bfloat162_rn(make_float2(c[2] + b0, c[3] + b1));
                }
            }
        }
    }
}

// ---------------------------------------------------------------------------
// Context + softmax normalize, pure bf16 P and V. Double-buffered cp.async
// pipeline; exp/prob-write phase is row-per-warp for coalesced STG (537MB).
// (256,2) ONLY — the 80-reg (256,3) clamp spills the fused exp loop
// (rounds 6, 11). Do not retry.
// ---------------------------------------------------------------------------
#define CT_PRAW 0
#define CT_PBUF 32768                       // 128 rows * 64 floats * 4B
#define CT_PH   (2 * CT_PBUF)               // 65536; 128x72 bf16 = 18432
#define CT_VH   (CT_PH + 18432)             // 83968; 2 x 64x72 bf16
#define CT_VBUF 9216
#define CT_STAT (CT_VH + 2 * CT_VBUF)       // 102400; rowm[128]+rinv[128]
#define CT_SMEM (CT_STAT + 1024)            // 103424

__global__ __launch_bounds__(256, 2) void mma_context(
    float* __restrict__ attn, const float* __restrict__ rowm,
    const float* __restrict__ rinv, __nv_bfloat16* __restrict__ ctxh)
{
    extern __shared__ __align__(16) char smem_raw[];
    const unsigned sb = sptr(smem_raw);
    __nv_bfloat16 (*Ph)[72] = (__nv_bfloat16(*)[72])(smem_raw + CT_PH);
    float* s_rowm = (float*)(smem_raw + CT_STAT);
    float* s_rinv = s_rowm + 128;

    const int t = threadIdx.x, lane = t & 31, w = t >> 5;
    const int wm = w & 3, wn = w >> 2;
    const int bh = blockIdx.y, r0 = blockIdx.x * 128;
    const size_t vbase = (size_t)bh * SS * DK;
    float* arow_base = attn + (size_t)bh * SS * SS + (size_t)r0 * SS;

    if (t < 128) {
        s_rowm[t] = rowm[(size_t)bh * SS + r0 + t];
        s_rinv[t] = rinv[(size_t)bh * SS + r0 + t];
    }

    float acc[2][4][4] = {};

    // chunk loader: raw P (128x64 fp32, 256B rows) + V (64x64 bf16)
    #define CT_LOAD(kk, buf) do {                                              \
        unsigned pb = sb + CT_PRAW + (buf) * CT_PBUF;                          \
        _Pragma("unroll")                                                      \
        for (int i = 0; i < 8; i++) {                                          \
            int ch = t + i * 256;                                              \
            int row = ch >> 4, seg = ch & 15;                                  \
            cp16(pb + row * 256 + seg * 16,                                    \
                 arow_base + (size_t)row * SS + (kk) + seg * 4);               \
        }                                                                      \
        unsigned vb = sb + CT_VH + (buf) * CT_VBUF;                            \
        _Pragma("unroll")                                                      \
        for (int i = 0; i < 2; i++) {                                          \
            int idx = t + i * 256;                                             \
            int vr = idx >> 3, vc = (idx & 7) * 8;                             \
            cp16(vb + vr * 144 + vc * 2,                                       \
                 g_vh + vbase + (size_t)((kk) + vr) * 64 + vc);                \
        }                                                                      \
    } while (0)

    CT_LOAD(0, 0);
    cp_commit();

    for (int it = 0; it < 32; it++) {
        const int buf = it & 1;
        if (it < 31) CT_LOAD((it + 1) * 64, buf ^ 1);
        cp_commit();
        cp_wait1();            // current chunk's group complete
        __syncthreads();

        {   // exp/normalize + coalesced prob write: warp w -> rows w*16..+15
            const float* praw = (const float*)(smem_raw + CT_PRAW + buf * CT_PBUF);
            #pragma unroll 4
            for (int r = 0; r < 16; r++) {
                int row = w * 16 + r;
                float m_ = s_rowm[row], ri_ = s_rinv[row];
                float2 v = *(const float2*)&praw[row * 64 + lane * 2];
                v.x = __expf(v.x - m_) * ri_;
                v.y = __expf(v.y - m_) * ri_;
                *(float2*)(arow_base + (size_t)row * SS + it * 64 + lane * 2) = v;
                *(__nv_bfloat162*)&Ph[row][lane * 2] =
                    __float22bfloat162_rn(v);
            }
        }
        __syncthreads();

        const unsigned vb = sb + CT_VH + buf * CT_VBUF;
        #pragma unroll
        for (int k2 = 0; k2 < 64; k2 += 16) {
            unsigned ah[2][4];
            #pragma unroll
            for (int mi = 0; mi < 2; mi++) {
                int r = wm * 32 + mi * 16 + (lane & 15);
                int c = k2 + ((lane >> 4) << 3);
                ldsm4(ah[mi], sptr(&Ph[r][c]));
            }
            #pragma unroll
            for (int g = 0; g < 2; g++) {
                int kr = k2 + (lane & 7) + (((lane >> 3) & 1) << 3);
                int nc = wn * 32 + g * 16 + ((lane >> 4) << 3);
                unsigned bh_[4];
                ldsm4t(bh_, vb + kr * 144 + nc * 2);
                #pragma unroll
                for (int mi = 0; mi < 2; mi++) {
                    mma_bf16(acc[mi][2*g],   ah[mi], &bh_[0]);
                    mma_bf16(acc[mi][2*g+1], ah[mi], &bh_[2]);
                }
            }
        }
        __syncthreads();
    }
    #undef CT_LOAD

    const int b = bh >> 3, h = bh & 7;
    #pragma unroll
    for (int mi = 0; mi < 2; mi++) {
        #pragma unroll
        for (int nf = 0; nf < 4; nf++) {
            float* c = acc[mi][nf];
            int m = r0 + wm * 32 + mi * 16 + (lane >> 2);
            int n = wn * 32 + nf * 8 + ((lane & 3) << 1);
            size_t idx = ((size_t)(b * SS + m)) * EMB + h * DK + n;
            *(__nv_bfloat162*)&ctxh[idx] =
                __float22bfloat162_rn(make_float2(c[0], c[1]));
            *(__nv_bfloat162*)&ctxh[idx + 8 * (size_t)EMB] =
                __float22bfloat162_rn(make_float2(c[2], c[3]));
        }
    }
}

// ---------------------------------------------------------------------------
// LayerNorm over 512.
// ---------------------------------------------------------------------------
__global__ __launch_bounds__(128) void ln_kernel(
    const float* __restrict__ gamma, const float* __restrict__ beta,
    float* __restrict__ out)
{
    const size_t row = blockIdx.x;
    const int t = threadIdx.x;
    const float* x = g_x + row * EMB;
    __shared__ float rs[4], rq[4];

    float4 v = ((const float4*)x)[t];
    float s  = v.x + v.y + v.z + v.w;
    float sq = v.x*v.x + v.y*v.y + v.z*v.z + v.w*v.w;
    #pragma unroll
    for (int o = 16; o; o >>= 1) {
        s  += __shfl_xor_sync(0xffffffffu, s,  o);
        sq += __shfl_xor_sync(0xffffffffu, sq, o);
    }
    if ((t & 31) == 0) { rs[t >> 5] = s; rq[t >> 5] = sq; }
    __syncthreads();
    s  = rs[0] + rs[1] + rs[2] + rs[3];
    sq = rq[0] + rq[1] + rq[2] + rq[3];

    float mu  = s * (1.0f / 512.0f);
    float var = sq * (1.0f / 512.0f) - mu * mu;
    float inv = rsqrtf(var + 1e-5f);

    float4 g = ((const float4*)gamma)[t];
    float4 bb = ((const float4*)beta)[t];
    float4 o;
    o.x = (v.x - mu) * inv * g.x + bb.x;
    o.y = (v.y - mu) * inv * g.y + bb.y;
    o.z = (v.z - mu) * inv * g.z + bb.z;
    o.w = (v.w - mu) * inv * g.w + bb.w;
    ((float4*)(out + row * EMB))[t] = o;
}

// ---------------------------------------------------------------------------
extern "C" void kernel_launch(void* const* d_in, const int* in_sizes, int n_in,
                              void* d_out, int out_size)
{
    const float* Q  = (const float*)d_in[0];
    const float* K  = (const float*)d_in[1];
    const float* V  = (const float*)d_in[2];
    const unsigned char* mask = (const unsigned char*)d_in[3];
    const float* Wq = (const float*)d_in[4];
    const float* bq = (const float*)d_in[5];
    const float* Wk = (const float*)d_in[6];
    const float* bk = (const float*)d_in[7];
    const float* Wv = (const float*)d_in[8];
    const float* bv = (const float*)d_in[9];
    const float* Wo = (const float*)d_in[10];
    const float* bo = (const float*)d_in[11];
    const float* gamma = (const float*)d_in[12];
    const float* beta  = (const float*)d_in[13];

    float* out  = (float*)d_out;
    float* attn = out + (size_t)BSROWS * EMB;

    __nv_bfloat16 *invh, *wvh, *woh, *vh, *ctxh;
    float *xp, *rowmp, *rinvp;
    cudaGetSymbolAddress((void**)&invh, g_invh);
    cudaGetSymbolAddress((void**)&wvh, g_wvh);
    cudaGetSymbolAddress((void**)&woh, g_woh);
    cudaGetSymbolAddress((void**)&vh, g_vh);
    cudaGetSymbolAddress((void**)&ctxh, g_ctxh);
    cudaGetSymbolAddress((void**)&xp,   g_x);
    cudaGetSymbolAddress((void**)&rowmp, g_rowm);
    cudaGetSymbolAddress((void**)&rinvp, g_rinv);

    cudaFuncSetAttribute(mma_scores, cudaFuncAttributeMaxDynamicSharedMemorySize,
                         SC_SMEM);
    cudaFuncSetAttribute(mma_qkproj, cudaFuncAttributeMaxDynamicSharedMemorySize,
                         GOff<1>::SMEM);
    cudaFuncSetAttribute(mma_gemm512<0,0,0>, cudaFuncAttributeMaxDynamicSharedMemorySize,
                         GOff<0>::SMEM);
    cudaFuncSetAttribute(mma_gemm512<1,0,0>, cudaFuncAttributeMaxDynamicSharedMemorySize,
                         GOff<0>::SMEM);
    cudaFuncSetAttribute(mma_context, cudaFuncAttributeMaxDynamicSharedMemorySize,
                         CT_SMEM);

    // merged conversions
    const int n4_in = BSROWS * EMB / 4;       // 1,048,576
    const int n4_w  = EMB * EMB / 4;          // 65,536
    const int nblk_in = (n4_in * 3 + 255) / 256;   // 12288
    const int nblk_w  = (n4_w * 4 + 255) / 256;    // 1024
    convert_all<<<nblk_in + nblk_w, 256>>>(Q, K, V, Wq, Wk, Wv, Wo,
                                           n4_in, nblk_in, n4_w);

    // Q + K projections in one launch (z = 0/1), then V projection
    dim3 qk_grid(EMB / 64, BSROWS / 128, 2);       // 8 x 64 x 2
    mma_qkproj<<<qk_grid, 256, GOff<1>::SMEM>>>(bq, bk);

    dim3 gemm_grid(EMB / 64, BSROWS / 128);        // 8 x 64
    mma_gemm512<0,0,0><<<gemm_grid, 256, GOff<0>::SMEM>>>(
        invh, nullptr, wvh, nullptr, bv, nullptr, vh, nullptr, nullptr);

    dim3 sc_grid(SS / 64, SS / 128, BH);           // 32 x 16 x 32
    mma_scores<<<sc_grid, 256, SC_SMEM>>>(mask, attn);

    softmax_stats<<<(BH * SS) / 8, 256>>>(rowmp, rinvp);

    dim3 ctx_grid(SS / 128, BH);                   // 16 x 32
    mma_context<<<ctx_grid, 256, CT_SMEM>>>(attn, rowmp, rinvp, ctxh);

    mma_gemm512<1,0,0><<<gemm_grid, 256, GOff<0>::SMEM>>>(
        ctxh, nullptr, woh, nullptr, bo, Q, nullptr, nullptr, xp);

    ln_kernel<<<BSROWS, 128>>>(gamma, beta, out);
}